// round 7
// baseline (speedup 1.0000x reference)
#include <cuda_runtime.h>
#include <math.h>
#include <stdint.h>

// Problem constants (GCNII_30794915512599)
#define NN   100000      // nodes
#define NE   1600000     // edges
#define FIN  512
#define HID  128
#define NC   64
#define NL   8

#define GEMM_BLOCKS ((NN + 127) / 128)          // 782
#define SC_BLOCKS   ((NE + 255) / 256)          // 6250
#define LPAD 132                                 // s-tile row stride (16B aligned)
#define LAYER_SMEM ((128 * LPAD + 2 * 16 * 128) * 4)   // 83,968 B

// ---------------- scratch (static __device__ — no allocations) ----------------
__device__ int   d_cnt[NN];      // zero-init at load; re-zeroed by k_out each launch
__device__ int   d_fill[NN];
__device__ int   d_rowptr[NN + 1];
__device__ float d_dinv[NN];
__device__ int   d_src[NE];
__device__ int   d_dst[NE];
__device__ int2  d_epack[NE];    // packed (src, weight-as-int)
__device__ float d_hA[(size_t)NN * HID];
__device__ float d_hB[(size_t)NN * HID];
__device__ float d_h0[(size_t)NN * HID];

// ---------------- cp.async helpers ----------------
__device__ __forceinline__ void cp_async16(uint32_t saddr, const void* gptr) {
    asm volatile("cp.async.ca.shared.global [%0], [%1], 16;"
                 :: "r"(saddr), "l"(gptr));
}
__device__ __forceinline__ void cp_commit() {
    asm volatile("cp.async.commit_group;");
}
__device__ __forceinline__ void cp_wait0() {
    asm volatile("cp.async.wait_group 0;");
}
__device__ __forceinline__ uint32_t smem_u32(const void* p) {
    return (uint32_t)__cvta_generic_to_shared(p);
}

// ---------------- edge prep (with inline per-warp dtype detection) ----------
// edge_index is logically int64 but JAX without x64 emits int32. int32 pairs
// read as uint64 are >= 2^32 whenever the high word is nonzero; true int64
// indices are < 100000. Each warp samples 64 words (false-negative prob ~0)
// so all warps reach the same verdict deterministically.
__global__ __launch_bounds__(256) void k_prep_edges(const void* eiv) {
    const int lane = threadIdx.x & 31;
    const unsigned long long* q = (const unsigned long long*)eiv;
    bool big = false;
#pragma unroll
    for (int k = 0; k < 2; k++) {
        int idx = (lane + k * 32) * 31;      // samples in [0, 1953] — in-bounds both ways
        big |= (q[idx] > 0xFFFFFFFFull);
    }
    bool is64 = !__any_sync(0xffffffff, big);

    int e = blockIdx.x * blockDim.x + threadIdx.x;
    if (e >= NE) return;
    int s, d;
    if (is64) {
        const long long* ei = (const long long*)eiv;
        s = (int)ei[e];
        d = (int)ei[(size_t)NE + e];
    } else {
        const int* ei = (const int*)eiv;
        s = ei[e];
        d = ei[NE + e];
    }
    s = min(max(s, 0), NN - 1);
    d = min(max(d, 0), NN - 1);
    d_src[e] = s;
    d_dst[e] = d;
    atomicAdd(&d_cnt[d], 1);
}

// single-block exclusive scan over d_cnt -> d_rowptr, fused with dinv compute
__global__ __launch_bounds__(1024) void k_scan_dinv() {
    __shared__ int buf[1024];
    const int t = threadIdx.x;
    const int CH = (NN + 1023) / 1024;   // 98
    const int start = t * CH;
    int s = 0;
    for (int j = 0; j < CH; j++) {
        int idx = start + j;
        if (idx < NN) s += d_cnt[idx];
    }
    buf[t] = s;
    __syncthreads();
    for (int off = 1; off < 1024; off <<= 1) {
        int v = (t >= off) ? buf[t - off] : 0;
        __syncthreads();
        buf[t] += v;
        __syncthreads();
    }
    int run = (t == 0) ? 0 : buf[t - 1];
    for (int j = 0; j < CH; j++) {
        int idx = start + j;
        if (idx < NN) {
            int c = d_cnt[idx];
            d_rowptr[idx] = run;
            d_dinv[idx] = rsqrtf((float)(c + 1));   // +1 self loop
            run += c;
        }
    }
    if (t == 1023) d_rowptr[NN] = buf[1023];
}

// ---------------- fused: input GEMM (blocks [0,782)) + CSR scatter (rest) ----
// gemm: h = x @ w_in + b_in ; h0 = h. BM=128,BN=128,BK=16, 8x8 tiles, dbuf.
__global__ __launch_bounds__(256, 2) void k_gemm_in_scatter(
        const float* __restrict__ X, const float* __restrict__ W,
        const float* __restrict__ B) {
    if (blockIdx.x >= GEMM_BLOCKS) {
        // ---- scatter branch ----
        int e = (blockIdx.x - GEMM_BLOCKS) * 256 + threadIdx.x;
        if (e < NE) {
            int s = d_src[e], d = d_dst[e];
            int pos = d_rowptr[d] + atomicAdd(&d_fill[d], 1);
            float w = d_dinv[s] * d_dinv[d];
            d_epack[pos] = make_int2(s, __float_as_int(w));
        }
        return;
    }
    __shared__ float As[2][16][132];
    __shared__ float Bs[2][16][128];
    const int tid = threadIdx.x;
    const int blockRow = blockIdx.x * 128;
    const int tx = tid & 15, ty = tid >> 4;
    const int ar = tid >> 2, ac4 = tid & 3;
    const int br = tid >> 5, bc4 = tid & 31;

    float acc[8][8];
#pragma unroll
    for (int i = 0; i < 8; i++)
#pragma unroll
        for (int j = 0; j < 8; j++) acc[i][j] = 0.f;

    {
#pragma unroll
        for (int j = 0; j < 2; j++) {
            int r = ar + j * 64;
            int grow = blockRow + r;
            float4 v = make_float4(0.f, 0.f, 0.f, 0.f);
            if (grow < NN)
                v = *(const float4*)(X + (size_t)grow * FIN + ac4 * 4);
            As[0][ac4 * 4 + 0][r] = v.x;
            As[0][ac4 * 4 + 1][r] = v.y;
            As[0][ac4 * 4 + 2][r] = v.z;
            As[0][ac4 * 4 + 3][r] = v.w;
        }
#pragma unroll
        for (int j = 0; j < 2; j++) {
            int r = br + j * 8;
            cp_async16(smem_u32(&Bs[0][r][bc4 * 4]), W + (size_t)r * HID + bc4 * 4);
        }
        cp_commit();
        cp_wait0();
    }
    __syncthreads();

    int p = 0;
    for (int k0 = 0; k0 < FIN; k0 += 16) {
        const int kn = k0 + 16;
        const bool more = (kn < FIN);
        float4 a0n, a1n;
        if (more) {
#pragma unroll
            for (int j = 0; j < 2; j++) {
                int r = br + j * 8;
                cp_async16(smem_u32(&Bs[p ^ 1][r][bc4 * 4]),
                           W + (size_t)(kn + r) * HID + bc4 * 4);
            }
            cp_commit();
            int g0 = blockRow + ar;
            int g1 = blockRow + ar + 64;
            a0n = make_float4(0.f, 0.f, 0.f, 0.f);
            a1n = make_float4(0.f, 0.f, 0.f, 0.f);
            if (g0 < NN) a0n = *(const float4*)(X + (size_t)g0 * FIN + kn + ac4 * 4);
            if (g1 < NN) a1n = *(const float4*)(X + (size_t)g1 * FIN + kn + ac4 * 4);
        }
#pragma unroll
        for (int kk = 0; kk < 16; kk++) {
            float a[8], b[8];
            *(float4*)&a[0] = *(float4*)&As[p][kk][ty * 8];
            *(float4*)&a[4] = *(float4*)&As[p][kk][ty * 8 + 4];
            *(float4*)&b[0] = *(float4*)&Bs[p][kk][tx * 8];
            *(float4*)&b[4] = *(float4*)&Bs[p][kk][tx * 8 + 4];
#pragma unroll
            for (int i = 0; i < 8; i++)
#pragma unroll
                for (int j = 0; j < 8; j++)
                    acc[i][j] += a[i] * b[j];
        }
        if (more) {
            As[p ^ 1][ac4 * 4 + 0][ar] = a0n.x;
            As[p ^ 1][ac4 * 4 + 1][ar] = a0n.y;
            As[p ^ 1][ac4 * 4 + 2][ar] = a0n.z;
            As[p ^ 1][ac4 * 4 + 3][ar] = a0n.w;
            As[p ^ 1][ac4 * 4 + 0][ar + 64] = a1n.x;
            As[p ^ 1][ac4 * 4 + 1][ar + 64] = a1n.y;
            As[p ^ 1][ac4 * 4 + 2][ar + 64] = a1n.z;
            As[p ^ 1][ac4 * 4 + 3][ar + 64] = a1n.w;
            cp_wait0();
        }
        __syncthreads();
        p ^= 1;
    }

    float bi[8];
    *(float4*)&bi[0] = *(const float4*)(B + tx * 8);
    *(float4*)&bi[4] = *(const float4*)(B + tx * 8 + 4);
#pragma unroll
    for (int i = 0; i < 8; i++) {
        int row = blockRow + ty * 8 + i;
        if (row >= NN) continue;
        float4 o0 = make_float4(acc[i][0] + bi[0], acc[i][1] + bi[1],
                                acc[i][2] + bi[2], acc[i][3] + bi[3]);
        float4 o1 = make_float4(acc[i][4] + bi[4], acc[i][5] + bi[5],
                                acc[i][6] + bi[6], acc[i][7] + bi[7]);
        float* hp  = d_hA + (size_t)row * HID + tx * 8;
        float* h0p = d_h0 + (size_t)row * HID + tx * 8;
        *(float4*)(hp)      = o0;
        *(float4*)(hp + 4)  = o1;
        *(float4*)(h0p)     = o0;
        *(float4*)(h0p + 4) = o1;
    }
}

// ---------------- fused layer: aggregate + GEMM + mix + ELU (race-free) -----
// reads hin (previous layer buffer), writes hout (other buffer).
// Phase A: warp-per-row gather of s = 0.9*(norm-adj @ hin) + 0.1*h0 into smem.
// Phase B: 128x128x128 GEMM from smem; epilogue elu((1-b)*s + b*(s@W)).
__global__ __launch_bounds__(256, 2) void k_layer(const float* __restrict__ W,
                                                  float beta, int parity) {
    extern __shared__ float smem[];
    float* st = smem;                        // [128][LPAD]
    float* Bq = smem + 128 * LPAD;           // [2][16][128]
    const float* hin  = parity ? d_hB : d_hA;
    float*       hout = parity ? d_hA : d_hB;
    const int tid = threadIdx.x;
    const int w = tid >> 5, lane = tid & 31;
    const int blockRow = blockIdx.x * 128;
    const float4* h4 = (const float4*)hin;

    // ---- Phase A: gather ----
#pragma unroll 1
    for (int r8 = 0; r8 < 16; r8++) {
        int rl = w + r8 * 8;                 // warp-interleaved rows
        int i = blockRow + rl;
        float4 o = make_float4(0.f, 0.f, 0.f, 0.f);
        if (i < NN) {
            float di = d_dinv[i];
            float wself = di * di;
            float4 hi = h4[(size_t)i * 32 + lane];
            float a0x = wself * hi.x, a0y = wself * hi.y;
            float a0z = wself * hi.z, a0w = wself * hi.w;
            float a1x = 0.f, a1y = 0.f, a1z = 0.f, a1w = 0.f;
            float a2x = 0.f, a2y = 0.f, a2z = 0.f, a2w = 0.f;
            float a3x = 0.f, a3y = 0.f, a3z = 0.f, a3w = 0.f;
            int beg = d_rowptr[i], end = d_rowptr[i + 1];
            int e = beg;
            int end4 = beg + ((end - beg) & ~3);
            for (; e < end4; e += 4) {
                int2 p0 = d_epack[e];
                int2 p1 = d_epack[e + 1];
                int2 p2 = d_epack[e + 2];
                int2 p3 = d_epack[e + 3];
                float4 v0 = __ldg(&h4[(size_t)p0.x * 32 + lane]);
                float4 v1 = __ldg(&h4[(size_t)p1.x * 32 + lane]);
                float4 v2 = __ldg(&h4[(size_t)p2.x * 32 + lane]);
                float4 v3 = __ldg(&h4[(size_t)p3.x * 32 + lane]);
                float w0 = __int_as_float(p0.y), w1 = __int_as_float(p1.y);
                float w2 = __int_as_float(p2.y), w3 = __int_as_float(p3.y);
                a0x += w0 * v0.x; a0y += w0 * v0.y; a0z += w0 * v0.z; a0w += w0 * v0.w;
                a1x += w1 * v1.x; a1y += w1 * v1.y; a1z += w1 * v1.z; a1w += w1 * v1.w;
                a2x += w2 * v2.x; a2y += w2 * v2.y; a2z += w2 * v2.z; a2w += w2 * v2.w;
                a3x += w3 * v3.x; a3y += w3 * v3.y; a3z += w3 * v3.z; a3w += w3 * v3.w;
            }
            for (; e < end; e++) {
                int2 p0 = d_epack[e];
                float w0 = __int_as_float(p0.y);
                float4 v0 = __ldg(&h4[(size_t)p0.x * 32 + lane]);
                a1x += w0 * v0.x; a1y += w0 * v0.y; a1z += w0 * v0.z; a1w += w0 * v0.w;
            }
            float4 h0v = ((const float4*)d_h0)[(size_t)i * 32 + lane];
            o.x = 0.9f * ((a0x + a1x) + (a2x + a3x)) + 0.1f * h0v.x;
            o.y = 0.9f * ((a0y + a1y) + (a2y + a3y)) + 0.1f * h0v.y;
            o.z = 0.9f * ((a0z + a1z) + (a2z + a3z)) + 0.1f * h0v.z;
            o.w = 0.9f * ((a0w + a1w) + (a2w + a3w)) + 0.1f * h0v.w;
        }
        *(float4*)&st[rl * LPAD + lane * 4] = o;
    }

    // ---- Phase B: GEMM from smem s-tile ----
    const int tx = tid & 15, ty = tid >> 4;
    const int br = tid >> 5, bc4 = tid & 31;
    float acc[8][8];
#pragma unroll
    for (int i = 0; i < 8; i++)
#pragma unroll
        for (int j = 0; j < 8; j++) acc[i][j] = 0.f;

    // prologue: W tile 0
#pragma unroll
    for (int j = 0; j < 2; j++) {
        int r = br + j * 8;
        cp_async16(smem_u32(&Bq[(0 * 16 + r) * 128 + bc4 * 4]),
                   W + (size_t)r * HID + bc4 * 4);
    }
    cp_commit();
    cp_wait0();
    __syncthreads();   // also fences phase-A st writes

    int p = 0;
    for (int k0 = 0; k0 < HID; k0 += 16) {
        const int kn = k0 + 16;
        const bool more = (kn < HID);
        if (more) {
#pragma unroll
            for (int j = 0; j < 2; j++) {
                int r = br + j * 8;
                cp_async16(smem_u32(&Bq[((p ^ 1) * 16 + r) * 128 + bc4 * 4]),
                           W + (size_t)(kn + r) * HID + bc4 * 4);
            }
            cp_commit();
        }
#pragma unroll
        for (int kk = 0; kk < 16; kk++) {
            float a[8], b[8];
#pragma unroll
            for (int i = 0; i < 8; i++)
                a[i] = st[(ty * 8 + i) * LPAD + k0 + kk];
            *(float4*)&b[0] = *(float4*)&Bq[(p * 16 + kk) * 128 + tx * 8];
            *(float4*)&b[4] = *(float4*)&Bq[(p * 16 + kk) * 128 + tx * 8 + 4];
#pragma unroll
            for (int i = 0; i < 8; i++)
#pragma unroll
                for (int j = 0; j < 8; j++)
                    acc[i][j] += a[i] * b[j];
        }
        if (more) cp_wait0();
        __syncthreads();
        p ^= 1;
    }

    // ---- epilogue: mix + ELU -> hout ----
    const float omb = 1.f - beta;
#pragma unroll
    for (int i = 0; i < 8; i++) {
        int rl = ty * 8 + i;
        int row = blockRow + rl;
        if (row >= NN) continue;
        float sv[8];
        *(float4*)&sv[0] = *(float4*)&st[rl * LPAD + tx * 8];
        *(float4*)&sv[4] = *(float4*)&st[rl * LPAD + tx * 8 + 4];
        float ov[8];
#pragma unroll
        for (int j = 0; j < 8; j++) {
            float v = omb * sv[j] + beta * acc[i][j];
            ov[j] = (v > 0.f) ? v : expm1f(v);
        }
        float* hp = hout + (size_t)row * HID + tx * 8;
        *(float4*)(hp)     = make_float4(ov[0], ov[1], ov[2], ov[3]);
        *(float4*)(hp + 4) = make_float4(ov[4], ov[5], ov[6], ov[7]);
    }
}

// ---------------- output GEMM + log_softmax (+ counter re-zero) -------------
__global__ __launch_bounds__(256) void k_out(const float* __restrict__ Wo,
                                             const float* __restrict__ Bo,
                                             float* __restrict__ out) {
    // re-zero counters for next launch (deterministic across graph replays)
    int gid = blockIdx.x * blockDim.x + threadIdx.x;
    if (gid < NN) { d_cnt[gid] = 0; d_fill[gid] = 0; }

    __shared__ float ws[128][64];   // 32 KB
    __shared__ float hs[32][128];   // 16 KB
    const int tid = threadIdx.x;
    const int base = blockIdx.x * 32;
#pragma unroll
    for (int j = 0; j < 8; j++) {
        int idx = tid + j * 256;
        int r = idx >> 4, c4 = idx & 15;
        *(float4*)&ws[r][c4 * 4] = *(const float4*)(Wo + (size_t)r * NC + c4 * 4);
    }
#pragma unroll
    for (int j = 0; j < 4; j++) {
        int idx = tid + j * 256;
        int r = idx >> 5, c4 = idx & 31;
        *(float4*)&hs[r][c4 * 4] =
            *(const float4*)(d_hA + (size_t)(base + r) * HID + c4 * 4);
    }
    __syncthreads();
    const int w = tid >> 5, lane = tid & 31;
    float b0 = Bo[lane], b1 = Bo[lane + 32];
    float acc[4][2];
#pragma unroll
    for (int r = 0; r < 4; r++) { acc[r][0] = 0.f; acc[r][1] = 0.f; }
    for (int k = 0; k < HID; k++) {
        float wv0 = ws[k][lane];
        float wv1 = ws[k][lane + 32];
#pragma unroll
        for (int r = 0; r < 4; r++) {
            float hv = hs[w * 4 + r][k];
            acc[r][0] += hv * wv0;
            acc[r][1] += hv * wv1;
        }
    }
#pragma unroll
    for (int r = 0; r < 4; r++) {
        int row = base + w * 4 + r;
        float v0 = acc[r][0] + b0;
        float v1 = acc[r][1] + b1;
        float m = fmaxf(v0, v1);
#pragma unroll
        for (int off = 16; off; off >>= 1)
            m = fmaxf(m, __shfl_xor_sync(0xffffffff, m, off));
        float ssum = expf(v0 - m) + expf(v1 - m);
#pragma unroll
        for (int off = 16; off; off >>= 1)
            ssum += __shfl_xor_sync(0xffffffff, ssum, off);
        float lse = m + logf(ssum);
        out[(size_t)row * NC + lane]      = v0 - lse;
        out[(size_t)row * NC + lane + 32] = v1 - lse;
    }
}

// ---------------- launch ----------------
extern "C" void kernel_launch(void* const* d_in, const int* in_sizes, int n_in,
                              void* d_out, int out_size) {
    const float* x      = (const float*)d_in[0];
    const void*  ei     = d_in[1];
    const float* w_in   = (const float*)d_in[2];
    const float* b_in   = (const float*)d_in[3];
    const float* conv_w = (const float*)d_in[4];
    const float* w_out  = (const float*)d_in[5];
    const float* b_out  = (const float*)d_in[6];
    float*       out    = (float*)d_out;

    cudaFuncSetAttribute(k_layer, cudaFuncAttributeMaxDynamicSharedMemorySize,
                         LAYER_SMEM);

    k_prep_edges<<<SC_BLOCKS, 256>>>(ei);                         // 0
    k_scan_dinv<<<1, 1024>>>();                                   // 1
    k_gemm_in_scatter<<<GEMM_BLOCKS + SC_BLOCKS, 256>>>(x, w_in, b_in); // 2

    for (int l = 0; l < NL; l++) {                                // 3..10
        float beta = (float)log(0.5 / (double)(l + 1) + 1.0);
        k_layer<<<GEMM_BLOCKS, 256, LAYER_SMEM>>>(
            conv_w + (size_t)l * HID * HID, beta, l & 1);
    }

    k_out<<<NN / 32, 256>>>(w_out, b_out, out);                   // 11
}

// round 8
// speedup vs baseline: 1.1120x; 1.1120x over previous
#include <cuda_runtime.h>
#include <math.h>
#include <stdint.h>

// Problem constants (GCNII_30794915512599)
#define NN   100000      // nodes
#define NE   1600000     // edges
#define FIN  512
#define HID  128
#define NC   64
#define NL   8

#define GEMM_BLOCKS ((NN + 127) / 128)          // 782
#define SC_BLOCKS   ((NE + 255) / 256)          // 6250

// ---------------- scratch (static __device__ — no allocations) ----------------
__device__ int   d_cnt[NN];      // zero-init at load; re-zeroed by k_out each launch
__device__ int   d_fill[NN];
__device__ int   d_rowptr[NN + 1];
__device__ float d_dinv[NN];
__device__ int   d_src[NE];
__device__ int   d_dst[NE];
__device__ int2  d_epack[NE];    // packed (src, weight-as-int)
__device__ float d_h [(size_t)NN * HID];
__device__ float d_s [(size_t)NN * HID];
__device__ float d_h0[(size_t)NN * HID];

// ---------------- cp.async helpers ----------------
__device__ __forceinline__ void cp_async16(uint32_t saddr, const void* gptr) {
    asm volatile("cp.async.ca.shared.global [%0], [%1], 16;"
                 :: "r"(saddr), "l"(gptr));
}
__device__ __forceinline__ void cp_commit() {
    asm volatile("cp.async.commit_group;");
}
__device__ __forceinline__ void cp_wait0() {
    asm volatile("cp.async.wait_group 0;");
}
__device__ __forceinline__ uint32_t smem_u32(const void* p) {
    return (uint32_t)__cvta_generic_to_shared(p);
}

// ---------------- edge prep (with inline per-warp dtype detection) ----------
// edge_index is logically int64 but JAX without x64 emits int32. int32 pairs
// read as uint64 are >= 2^32 whenever the high word is nonzero; true int64
// indices are < 100000.
__global__ __launch_bounds__(256) void k_prep_edges(const void* eiv) {
    const int lane = threadIdx.x & 31;
    const unsigned long long* q = (const unsigned long long*)eiv;
    bool big = false;
#pragma unroll
    for (int k = 0; k < 2; k++) {
        int idx = (lane + k * 32) * 31;      // samples in [0, 1953]
        big |= (q[idx] > 0xFFFFFFFFull);
    }
    bool is64 = !__any_sync(0xffffffff, big);

    int e = blockIdx.x * blockDim.x + threadIdx.x;
    if (e >= NE) return;
    int s, d;
    if (is64) {
        const long long* ei = (const long long*)eiv;
        s = (int)ei[e];
        d = (int)ei[(size_t)NE + e];
    } else {
        const int* ei = (const int*)eiv;
        s = ei[e];
        d = ei[NE + e];
    }
    s = min(max(s, 0), NN - 1);
    d = min(max(d, 0), NN - 1);
    d_src[e] = s;
    d_dst[e] = d;
    atomicAdd(&d_cnt[d], 1);
}

// single-block exclusive scan over d_cnt -> d_rowptr, fused with dinv compute
__global__ __launch_bounds__(1024) void k_scan_dinv() {
    __shared__ int buf[1024];
    const int t = threadIdx.x;
    const int CH = (NN + 1023) / 1024;   // 98
    const int start = t * CH;
    int s = 0;
    for (int j = 0; j < CH; j++) {
        int idx = start + j;
        if (idx < NN) s += d_cnt[idx];
    }
    buf[t] = s;
    __syncthreads();
    for (int off = 1; off < 1024; off <<= 1) {
        int v = (t >= off) ? buf[t - off] : 0;
        __syncthreads();
        buf[t] += v;
        __syncthreads();
    }
    int run = (t == 0) ? 0 : buf[t - 1];
    for (int j = 0; j < CH; j++) {
        int idx = start + j;
        if (idx < NN) {
            int c = d_cnt[idx];
            d_rowptr[idx] = run;
            d_dinv[idx] = rsqrtf((float)(c + 1));   // +1 self loop
            run += c;
        }
    }
    if (t == 1023) d_rowptr[NN] = buf[1023];
}

// ---------------- fused: input GEMM (blocks [0,782)) + CSR scatter (rest) ----
__global__ __launch_bounds__(256, 2) void k_gemm_in_scatter(
        const float* __restrict__ X, const float* __restrict__ W,
        const float* __restrict__ B) {
    if (blockIdx.x >= GEMM_BLOCKS) {
        int e = (blockIdx.x - GEMM_BLOCKS) * 256 + threadIdx.x;
        if (e < NE) {
            int s = d_src[e], d = d_dst[e];
            int pos = d_rowptr[d] + atomicAdd(&d_fill[d], 1);
            float w = d_dinv[s] * d_dinv[d];
            d_epack[pos] = make_int2(s, __float_as_int(w));
        }
        return;
    }
    __shared__ float As[2][16][132];
    __shared__ float Bs[2][16][128];
    const int tid = threadIdx.x;
    const int blockRow = blockIdx.x * 128;
    const int tx = tid & 15, ty = tid >> 4;
    const int ar = tid >> 2, ac4 = tid & 3;
    const int br = tid >> 5, bc4 = tid & 31;

    float acc[8][8];
#pragma unroll
    for (int i = 0; i < 8; i++)
#pragma unroll
        for (int j = 0; j < 8; j++) acc[i][j] = 0.f;

    {
#pragma unroll
        for (int j = 0; j < 2; j++) {
            int r = ar + j * 64;
            int grow = blockRow + r;
            float4 v = make_float4(0.f, 0.f, 0.f, 0.f);
            if (grow < NN)
                v = *(const float4*)(X + (size_t)grow * FIN + ac4 * 4);
            As[0][ac4 * 4 + 0][r] = v.x;
            As[0][ac4 * 4 + 1][r] = v.y;
            As[0][ac4 * 4 + 2][r] = v.z;
            As[0][ac4 * 4 + 3][r] = v.w;
        }
#pragma unroll
        for (int j = 0; j < 2; j++) {
            int r = br + j * 8;
            cp_async16(smem_u32(&Bs[0][r][bc4 * 4]), W + (size_t)r * HID + bc4 * 4);
        }
        cp_commit();
        cp_wait0();
    }
    __syncthreads();

    int p = 0;
    for (int k0 = 0; k0 < FIN; k0 += 16) {
        const int kn = k0 + 16;
        const bool more = (kn < FIN);
        float4 a0n, a1n;
        if (more) {
#pragma unroll
            for (int j = 0; j < 2; j++) {
                int r = br + j * 8;
                cp_async16(smem_u32(&Bs[p ^ 1][r][bc4 * 4]),
                           W + (size_t)(kn + r) * HID + bc4 * 4);
            }
            cp_commit();
            int g0 = blockRow + ar;
            int g1 = blockRow + ar + 64;
            a0n = make_float4(0.f, 0.f, 0.f, 0.f);
            a1n = make_float4(0.f, 0.f, 0.f, 0.f);
            if (g0 < NN) a0n = *(const float4*)(X + (size_t)g0 * FIN + kn + ac4 * 4);
            if (g1 < NN) a1n = *(const float4*)(X + (size_t)g1 * FIN + kn + ac4 * 4);
        }
#pragma unroll
        for (int kk = 0; kk < 16; kk++) {
            float a[8], b[8];
            *(float4*)&a[0] = *(float4*)&As[p][kk][ty * 8];
            *(float4*)&a[4] = *(float4*)&As[p][kk][ty * 8 + 4];
            *(float4*)&b[0] = *(float4*)&Bs[p][kk][tx * 8];
            *(float4*)&b[4] = *(float4*)&Bs[p][kk][tx * 8 + 4];
#pragma unroll
            for (int i = 0; i < 8; i++)
#pragma unroll
                for (int j = 0; j < 8; j++)
                    acc[i][j] += a[i] * b[j];
        }
        if (more) {
            As[p ^ 1][ac4 * 4 + 0][ar] = a0n.x;
            As[p ^ 1][ac4 * 4 + 1][ar] = a0n.y;
            As[p ^ 1][ac4 * 4 + 2][ar] = a0n.z;
            As[p ^ 1][ac4 * 4 + 3][ar] = a0n.w;
            As[p ^ 1][ac4 * 4 + 0][ar + 64] = a1n.x;
            As[p ^ 1][ac4 * 4 + 1][ar + 64] = a1n.y;
            As[p ^ 1][ac4 * 4 + 2][ar + 64] = a1n.z;
            As[p ^ 1][ac4 * 4 + 3][ar + 64] = a1n.w;
            cp_wait0();
        }
        __syncthreads();
        p ^= 1;
    }

    float bi[8];
    *(float4*)&bi[0] = *(const float4*)(B + tx * 8);
    *(float4*)&bi[4] = *(const float4*)(B + tx * 8 + 4);
#pragma unroll
    for (int i = 0; i < 8; i++) {
        int row = blockRow + ty * 8 + i;
        if (row >= NN) continue;
        float4 o0 = make_float4(acc[i][0] + bi[0], acc[i][1] + bi[1],
                                acc[i][2] + bi[2], acc[i][3] + bi[3]);
        float4 o1 = make_float4(acc[i][4] + bi[4], acc[i][5] + bi[5],
                                acc[i][6] + bi[6], acc[i][7] + bi[7]);
        float* hp  = d_h  + (size_t)row * HID + tx * 8;
        float* h0p = d_h0 + (size_t)row * HID + tx * 8;
        *(float4*)(hp)      = o0;
        *(float4*)(hp + 4)  = o1;
        *(float4*)(h0p)     = o0;
        *(float4*)(h0p + 4) = o1;
    }
}

// ---------------- aggregation: s = 0.9*(norm-adj @ h) + 0.1*h0 ----------------
// one warp per node, float4 per lane, 8-way edge unroll (MLP=8), no smem
__global__ __launch_bounds__(256) void k_agg() {
    int i = blockIdx.x * 8 + (threadIdx.x >> 5);
    if (i >= NN) return;
    int lane = threadIdx.x & 31;
    const float4* h4 = (const float4*)d_h;
    float di = d_dinv[i];
    float wself = di * di;
    float4 hi = h4[(size_t)i * 32 + lane];
    float4 A0 = make_float4(wself * hi.x, wself * hi.y, wself * hi.z, wself * hi.w);
    float4 A1 = make_float4(0.f, 0.f, 0.f, 0.f);
    float4 A2 = make_float4(0.f, 0.f, 0.f, 0.f);
    float4 A3 = make_float4(0.f, 0.f, 0.f, 0.f);
    int beg = d_rowptr[i], end = d_rowptr[i + 1];
    int n = end - beg;
    int e = beg;
    int end8 = beg + (n & ~7);
    for (; e < end8; e += 8) {
        int2 p0 = d_epack[e];
        int2 p1 = d_epack[e + 1];
        int2 p2 = d_epack[e + 2];
        int2 p3 = d_epack[e + 3];
        int2 p4 = d_epack[e + 4];
        int2 p5 = d_epack[e + 5];
        int2 p6 = d_epack[e + 6];
        int2 p7 = d_epack[e + 7];
        float4 v0 = __ldg(&h4[(size_t)p0.x * 32 + lane]);
        float4 v1 = __ldg(&h4[(size_t)p1.x * 32 + lane]);
        float4 v2 = __ldg(&h4[(size_t)p2.x * 32 + lane]);
        float4 v3 = __ldg(&h4[(size_t)p3.x * 32 + lane]);
        float4 v4 = __ldg(&h4[(size_t)p4.x * 32 + lane]);
        float4 v5 = __ldg(&h4[(size_t)p5.x * 32 + lane]);
        float4 v6 = __ldg(&h4[(size_t)p6.x * 32 + lane]);
        float4 v7 = __ldg(&h4[(size_t)p7.x * 32 + lane]);
        float w0 = __int_as_float(p0.y), w1 = __int_as_float(p1.y);
        float w2 = __int_as_float(p2.y), w3 = __int_as_float(p3.y);
        float w4 = __int_as_float(p4.y), w5 = __int_as_float(p5.y);
        float w6 = __int_as_float(p6.y), w7 = __int_as_float(p7.y);
        A0.x += w0 * v0.x; A0.y += w0 * v0.y; A0.z += w0 * v0.z; A0.w += w0 * v0.w;
        A1.x += w1 * v1.x; A1.y += w1 * v1.y; A1.z += w1 * v1.z; A1.w += w1 * v1.w;
        A2.x += w2 * v2.x; A2.y += w2 * v2.y; A2.z += w2 * v2.z; A2.w += w2 * v2.w;
        A3.x += w3 * v3.x; A3.y += w3 * v3.y; A3.z += w3 * v3.z; A3.w += w3 * v3.w;
        A0.x += w4 * v4.x; A0.y += w4 * v4.y; A0.z += w4 * v4.z; A0.w += w4 * v4.w;
        A1.x += w5 * v5.x; A1.y += w5 * v5.y; A1.z += w5 * v5.z; A1.w += w5 * v5.w;
        A2.x += w6 * v6.x; A2.y += w6 * v6.y; A2.z += w6 * v6.z; A2.w += w6 * v6.w;
        A3.x += w7 * v7.x; A3.y += w7 * v7.y; A3.z += w7 * v7.z; A3.w += w7 * v7.w;
    }
    for (; e < end; e++) {
        int2 p0 = d_epack[e];
        float w0 = __int_as_float(p0.y);
        float4 v0 = __ldg(&h4[(size_t)p0.x * 32 + lane]);
        A1.x += w0 * v0.x; A1.y += w0 * v0.y; A1.z += w0 * v0.z; A1.w += w0 * v0.w;
    }
    float4 h0v = ((const float4*)d_h0)[(size_t)i * 32 + lane];
    float4 o;
    o.x = 0.9f * ((A0.x + A1.x) + (A2.x + A3.x)) + 0.1f * h0v.x;
    o.y = 0.9f * ((A0.y + A1.y) + (A2.y + A3.y)) + 0.1f * h0v.y;
    o.z = 0.9f * ((A0.z + A1.z) + (A2.z + A3.z)) + 0.1f * h0v.z;
    o.w = 0.9f * ((A0.w + A1.w) + (A2.w + A3.w)) + 0.1f * h0v.w;
    ((float4*)d_s)[(size_t)i * 32 + lane] = o;
}

// ---------------- layer GEMM + identity-map mix + ELU ----------------
// h = elu((1-beta)*s + beta*(s @ W)); double-buffered, cp.async B
__global__ __launch_bounds__(256, 2) void k_gemm_layer(const float* __restrict__ W,
                                                       float beta) {
    __shared__ float As[2][16][132];
    __shared__ float Bs[2][16][128];
    const int tid = threadIdx.x;
    const int blockRow = blockIdx.x * 128;
    const int tx = tid & 15, ty = tid >> 4;
    const int ar = tid >> 2, ac4 = tid & 3;
    const int br = tid >> 5, bc4 = tid & 31;

    float acc[8][8];
#pragma unroll
    for (int i = 0; i < 8; i++)
#pragma unroll
        for (int j = 0; j < 8; j++) acc[i][j] = 0.f;

    {
#pragma unroll
        for (int j = 0; j < 2; j++) {
            int r = ar + j * 64;
            int grow = blockRow + r;
            float4 v = make_float4(0.f, 0.f, 0.f, 0.f);
            if (grow < NN)
                v = *(const float4*)(d_s + (size_t)grow * HID + ac4 * 4);
            As[0][ac4 * 4 + 0][r] = v.x;
            As[0][ac4 * 4 + 1][r] = v.y;
            As[0][ac4 * 4 + 2][r] = v.z;
            As[0][ac4 * 4 + 3][r] = v.w;
        }
#pragma unroll
        for (int j = 0; j < 2; j++) {
            int r = br + j * 8;
            cp_async16(smem_u32(&Bs[0][r][bc4 * 4]),
                       W + (size_t)r * HID + bc4 * 4);
        }
        cp_commit();
        cp_wait0();
    }
    __syncthreads();

    int p = 0;
    for (int k0 = 0; k0 < HID; k0 += 16) {
        const int kn = k0 + 16;
        const bool more = (kn < HID);
        float4 a0n, a1n;
        if (more) {
#pragma unroll
            for (int j = 0; j < 2; j++) {
                int r = br + j * 8;
                cp_async16(smem_u32(&Bs[p ^ 1][r][bc4 * 4]),
                           W + (size_t)(kn + r) * HID + bc4 * 4);
            }
            cp_commit();
            int g0 = blockRow + ar;
            int g1 = blockRow + ar + 64;
            a0n = make_float4(0.f, 0.f, 0.f, 0.f);
            a1n = make_float4(0.f, 0.f, 0.f, 0.f);
            if (g0 < NN) a0n = *(const float4*)(d_s + (size_t)g0 * HID + kn + ac4 * 4);
            if (g1 < NN) a1n = *(const float4*)(d_s + (size_t)g1 * HID + kn + ac4 * 4);
        }
#pragma unroll
        for (int kk = 0; kk < 16; kk++) {
            float a[8], b[8];
            *(float4*)&a[0] = *(float4*)&As[p][kk][ty * 8];
            *(float4*)&a[4] = *(float4*)&As[p][kk][ty * 8 + 4];
            *(float4*)&b[0] = *(float4*)&Bs[p][kk][tx * 8];
            *(float4*)&b[4] = *(float4*)&Bs[p][kk][tx * 8 + 4];
#pragma unroll
            for (int i = 0; i < 8; i++)
#pragma unroll
                for (int j = 0; j < 8; j++)
                    acc[i][j] += a[i] * b[j];
        }
        if (more) {
            As[p ^ 1][ac4 * 4 + 0][ar] = a0n.x;
            As[p ^ 1][ac4 * 4 + 1][ar] = a0n.y;
            As[p ^ 1][ac4 * 4 + 2][ar] = a0n.z;
            As[p ^ 1][ac4 * 4 + 3][ar] = a0n.w;
            As[p ^ 1][ac4 * 4 + 0][ar + 64] = a1n.x;
            As[p ^ 1][ac4 * 4 + 1][ar + 64] = a1n.y;
            As[p ^ 1][ac4 * 4 + 2][ar + 64] = a1n.z;
            As[p ^ 1][ac4 * 4 + 3][ar + 64] = a1n.w;
            cp_wait0();
        }
        __syncthreads();
        p ^= 1;
    }

    const float omb = 1.f - beta;
#pragma unroll
    for (int i = 0; i < 8; i++) {
        int row = blockRow + ty * 8 + i;
        if (row >= NN) continue;
        const float* sp = d_s + (size_t)row * HID + tx * 8;
        float4 s0 = *(const float4*)(sp);
        float4 s1 = *(const float4*)(sp + 4);
        float sv[8] = {s0.x, s0.y, s0.z, s0.w, s1.x, s1.y, s1.z, s1.w};
        float ov[8];
#pragma unroll
        for (int j = 0; j < 8; j++) {
            float v = omb * sv[j] + beta * acc[i][j];
            ov[j] = (v > 0.f) ? v : expm1f(v);
        }
        float* hp = d_h + (size_t)row * HID + tx * 8;
        *(float4*)(hp)     = make_float4(ov[0], ov[1], ov[2], ov[3]);
        *(float4*)(hp + 4) = make_float4(ov[4], ov[5], ov[6], ov[7]);
    }
}

// ---------------- output GEMM + log_softmax (+ counter re-zero) -------------
__global__ __launch_bounds__(256) void k_out(const float* __restrict__ Wo,
                                             const float* __restrict__ Bo,
                                             float* __restrict__ out) {
    int gid = blockIdx.x * blockDim.x + threadIdx.x;
    if (gid < NN) { d_cnt[gid] = 0; d_fill[gid] = 0; }

    __shared__ float ws[128][64];   // 32 KB
    __shared__ float hs[32][128];   // 16 KB
    const int tid = threadIdx.x;
    const int base = blockIdx.x * 32;
#pragma unroll
    for (int j = 0; j < 8; j++) {
        int idx = tid + j * 256;
        int r = idx >> 4, c4 = idx & 15;
        *(float4*)&ws[r][c4 * 4] = *(const float4*)(Wo + (size_t)r * NC + c4 * 4);
    }
#pragma unroll
    for (int j = 0; j < 4; j++) {
        int idx = tid + j * 256;
        int r = idx >> 5, c4 = idx & 31;
        *(float4*)&hs[r][c4 * 4] =
            *(const float4*)(d_h + (size_t)(base + r) * HID + c4 * 4);
    }
    __syncthreads();
    const int w = tid >> 5, lane = tid & 31;
    float b0 = Bo[lane], b1 = Bo[lane + 32];
    float acc[4][2];
#pragma unroll
    for (int r = 0; r < 4; r++) { acc[r][0] = 0.f; acc[r][1] = 0.f; }
    for (int k = 0; k < HID; k++) {
        float wv0 = ws[k][lane];
        float wv1 = ws[k][lane + 32];
#pragma unroll
        for (int r = 0; r < 4; r++) {
            float hv = hs[w * 4 + r][k];
            acc[r][0] += hv * wv0;
            acc[r][1] += hv * wv1;
        }
    }
#pragma unroll
    for (int r = 0; r < 4; r++) {
        int row = base + w * 4 + r;
        float v0 = acc[r][0] + b0;
        float v1 = acc[r][1] + b1;
        float m = fmaxf(v0, v1);
#pragma unroll
        for (int off = 16; off; off >>= 1)
            m = fmaxf(m, __shfl_xor_sync(0xffffffff, m, off));
        float ssum = expf(v0 - m) + expf(v1 - m);
#pragma unroll
        for (int off = 16; off; off >>= 1)
            ssum += __shfl_xor_sync(0xffffffff, ssum, off);
        float lse = m + logf(ssum);
        out[(size_t)row * NC + lane]      = v0 - lse;
        out[(size_t)row * NC + lane + 32] = v1 - lse;
    }
}

// ---------------- launch ----------------
extern "C" void kernel_launch(void* const* d_in, const int* in_sizes, int n_in,
                              void* d_out, int out_size) {
    const float* x      = (const float*)d_in[0];
    const void*  ei     = d_in[1];
    const float* w_in   = (const float*)d_in[2];
    const float* b_in   = (const float*)d_in[3];
    const float* conv_w = (const float*)d_in[4];
    const float* w_out  = (const float*)d_in[5];
    const float* b_out  = (const float*)d_in[6];
    float*       out    = (float*)d_out;

    k_prep_edges<<<SC_BLOCKS, 256>>>(ei);                               // 0
    k_scan_dinv<<<1, 1024>>>();                                         // 1
    k_gemm_in_scatter<<<GEMM_BLOCKS + SC_BLOCKS, 256>>>(x, w_in, b_in); // 2

    for (int l = 0; l < NL; l++) {                                      // 3..18
        float beta = (float)log(0.5 / (double)(l + 1) + 1.0);
        k_agg<<<(NN + 7) / 8, 256>>>();           // slot 3 = profiled
        k_gemm_layer<<<GEMM_BLOCKS, 256>>>(conv_w + (size_t)l * HID * HID, beta);
    }

    k_out<<<NN / 32, 256>>>(w_out, b_out, out);
}

// round 9
// speedup vs baseline: 1.1216x; 1.0086x over previous
#include <cuda_runtime.h>
#include <math.h>
#include <stdint.h>

// Problem constants (GCNII_30794915512599)
#define NN   100000      // nodes
#define NE   1600000     // edges
#define FIN  512
#define HID  128
#define NC   64
#define NL   8

#define GEMM_BLOCKS ((NN + 127) / 128)          // 782
#define SC_BLOCKS   ((NE + 255) / 256)          // 6250

// ---------------- scratch (static __device__ — no allocations) ----------------
__device__ int   d_cnt[NN];      // zero-init at load; re-zeroed by k_out each launch
__device__ int   d_fill[NN];
__device__ int   d_rowptr[NN + 1];
__device__ float d_dinv[NN];
__device__ int   d_src[NE];
__device__ int   d_dst[NE];
__device__ int2  d_epack[NE];    // packed (src, weight-as-int)
__device__ float d_h [(size_t)NN * HID];
__device__ float d_s [(size_t)NN * HID];
__device__ float d_h0[(size_t)NN * HID];

// ---------------- cp.async helpers ----------------
__device__ __forceinline__ void cp_async16(uint32_t saddr, const void* gptr) {
    asm volatile("cp.async.ca.shared.global [%0], [%1], 16;"
                 :: "r"(saddr), "l"(gptr));
}
__device__ __forceinline__ void cp_commit() {
    asm volatile("cp.async.commit_group;");
}
__device__ __forceinline__ void cp_wait0() {
    asm volatile("cp.async.wait_group 0;");
}
__device__ __forceinline__ uint32_t smem_u32(const void* p) {
    return (uint32_t)__cvta_generic_to_shared(p);
}

// ---------------- edge prep (with inline per-warp dtype detection) ----------
// edge_index is logically int64 but JAX without x64 emits int32. int32 pairs
// read as uint64 are >= 2^32 whenever the high word is nonzero; true int64
// indices are < 100000.
__global__ __launch_bounds__(256) void k_prep_edges(const void* eiv) {
    const int lane = threadIdx.x & 31;
    const unsigned long long* q = (const unsigned long long*)eiv;
    bool big = false;
#pragma unroll
    for (int k = 0; k < 2; k++) {
        int idx = (lane + k * 32) * 31;      // samples in [0, 1953]
        big |= (q[idx] > 0xFFFFFFFFull);
    }
    bool is64 = !__any_sync(0xffffffff, big);

    int e = blockIdx.x * blockDim.x + threadIdx.x;
    if (e >= NE) return;
    int s, d;
    if (is64) {
        const long long* ei = (const long long*)eiv;
        s = (int)ei[e];
        d = (int)ei[(size_t)NE + e];
    } else {
        const int* ei = (const int*)eiv;
        s = ei[e];
        d = ei[NE + e];
    }
    s = min(max(s, 0), NN - 1);
    d = min(max(d, 0), NN - 1);
    d_src[e] = s;
    d_dst[e] = d;
    atomicAdd(&d_cnt[d], 1);
}

// single-block exclusive scan over d_cnt -> d_rowptr, fused with dinv compute
__global__ __launch_bounds__(1024) void k_scan_dinv() {
    __shared__ int buf[1024];
    const int t = threadIdx.x;
    const int CH = (NN + 1023) / 1024;   // 98
    const int start = t * CH;
    int s = 0;
    for (int j = 0; j < CH; j++) {
        int idx = start + j;
        if (idx < NN) s += d_cnt[idx];
    }
    buf[t] = s;
    __syncthreads();
    for (int off = 1; off < 1024; off <<= 1) {
        int v = (t >= off) ? buf[t - off] : 0;
        __syncthreads();
        buf[t] += v;
        __syncthreads();
    }
    int run = (t == 0) ? 0 : buf[t - 1];
    for (int j = 0; j < CH; j++) {
        int idx = start + j;
        if (idx < NN) {
            int c = d_cnt[idx];
            d_rowptr[idx] = run;
            d_dinv[idx] = rsqrtf((float)(c + 1));   // +1 self loop
            run += c;
        }
    }
    if (t == 1023) d_rowptr[NN] = buf[1023];
}

// ---------------- fused: input GEMM (blocks [0,782)) + CSR scatter (rest) ----
__global__ __launch_bounds__(256, 2) void k_gemm_in_scatter(
        const float* __restrict__ X, const float* __restrict__ W,
        const float* __restrict__ B) {
    if (blockIdx.x >= GEMM_BLOCKS) {
        int e = (blockIdx.x - GEMM_BLOCKS) * 256 + threadIdx.x;
        if (e < NE) {
            int s = d_src[e], d = d_dst[e];
            int pos = d_rowptr[d] + atomicAdd(&d_fill[d], 1);
            float w = d_dinv[s] * d_dinv[d];
            d_epack[pos] = make_int2(s, __float_as_int(w));
        }
        return;
    }
    __shared__ float As[2][16][132];
    __shared__ float Bs[2][16][128];
    const int tid = threadIdx.x;
    const int blockRow = blockIdx.x * 128;
    const int tx = tid & 15, ty = tid >> 4;
    const int ar = tid >> 2, ac4 = tid & 3;
    const int br = tid >> 5, bc4 = tid & 31;

    float acc[8][8];
#pragma unroll
    for (int i = 0; i < 8; i++)
#pragma unroll
        for (int j = 0; j < 8; j++) acc[i][j] = 0.f;

    {
#pragma unroll
        for (int j = 0; j < 2; j++) {
            int r = ar + j * 64;
            int grow = blockRow + r;
            float4 v = make_float4(0.f, 0.f, 0.f, 0.f);
            if (grow < NN)
                v = *(const float4*)(X + (size_t)grow * FIN + ac4 * 4);
            As[0][ac4 * 4 + 0][r] = v.x;
            As[0][ac4 * 4 + 1][r] = v.y;
            As[0][ac4 * 4 + 2][r] = v.z;
            As[0][ac4 * 4 + 3][r] = v.w;
        }
#pragma unroll
        for (int j = 0; j < 2; j++) {
            int r = br + j * 8;
            cp_async16(smem_u32(&Bs[0][r][bc4 * 4]), W + (size_t)r * HID + bc4 * 4);
        }
        cp_commit();
        cp_wait0();
    }
    __syncthreads();

    int p = 0;
    for (int k0 = 0; k0 < FIN; k0 += 16) {
        const int kn = k0 + 16;
        const bool more = (kn < FIN);
        float4 a0n, a1n;
        if (more) {
#pragma unroll
            for (int j = 0; j < 2; j++) {
                int r = br + j * 8;
                cp_async16(smem_u32(&Bs[p ^ 1][r][bc4 * 4]),
                           W + (size_t)(kn + r) * HID + bc4 * 4);
            }
            cp_commit();
            int g0 = blockRow + ar;
            int g1 = blockRow + ar + 64;
            a0n = make_float4(0.f, 0.f, 0.f, 0.f);
            a1n = make_float4(0.f, 0.f, 0.f, 0.f);
            if (g0 < NN) a0n = *(const float4*)(X + (size_t)g0 * FIN + kn + ac4 * 4);
            if (g1 < NN) a1n = *(const float4*)(X + (size_t)g1 * FIN + kn + ac4 * 4);
        }
#pragma unroll
        for (int kk = 0; kk < 16; kk++) {
            float a[8], b[8];
            *(float4*)&a[0] = *(float4*)&As[p][kk][ty * 8];
            *(float4*)&a[4] = *(float4*)&As[p][kk][ty * 8 + 4];
            *(float4*)&b[0] = *(float4*)&Bs[p][kk][tx * 8];
            *(float4*)&b[4] = *(float4*)&Bs[p][kk][tx * 8 + 4];
#pragma unroll
            for (int i = 0; i < 8; i++)
#pragma unroll
                for (int j = 0; j < 8; j++)
                    acc[i][j] += a[i] * b[j];
        }
        if (more) {
            As[p ^ 1][ac4 * 4 + 0][ar] = a0n.x;
            As[p ^ 1][ac4 * 4 + 1][ar] = a0n.y;
            As[p ^ 1][ac4 * 4 + 2][ar] = a0n.z;
            As[p ^ 1][ac4 * 4 + 3][ar] = a0n.w;
            As[p ^ 1][ac4 * 4 + 0][ar + 64] = a1n.x;
            As[p ^ 1][ac4 * 4 + 1][ar + 64] = a1n.y;
            As[p ^ 1][ac4 * 4 + 2][ar + 64] = a1n.z;
            As[p ^ 1][ac4 * 4 + 3][ar + 64] = a1n.w;
            cp_wait0();
        }
        __syncthreads();
        p ^= 1;
    }

    float bi[8];
    *(float4*)&bi[0] = *(const float4*)(B + tx * 8);
    *(float4*)&bi[4] = *(const float4*)(B + tx * 8 + 4);
#pragma unroll
    for (int i = 0; i < 8; i++) {
        int row = blockRow + ty * 8 + i;
        if (row >= NN) continue;
        float4 o0 = make_float4(acc[i][0] + bi[0], acc[i][1] + bi[1],
                                acc[i][2] + bi[2], acc[i][3] + bi[3]);
        float4 o1 = make_float4(acc[i][4] + bi[4], acc[i][5] + bi[5],
                                acc[i][6] + bi[6], acc[i][7] + bi[7]);
        float* hp  = d_h  + (size_t)row * HID + tx * 8;
        float* h0p = d_h0 + (size_t)row * HID + tx * 8;
        *(float4*)(hp)      = o0;
        *(float4*)(hp + 4)  = o1;
        *(float4*)(h0p)     = o0;
        *(float4*)(h0p + 4) = o1;
    }
}

// ---------------- aggregation: s = 0.9*(norm-adj @ h) + 0.1*h0 ----------------
// one warp per node, float4 per lane, 8-way edge unroll (MLP=8), no smem
__global__ __launch_bounds__(256) void k_agg() {
    int i = blockIdx.x * 8 + (threadIdx.x >> 5);
    if (i >= NN) return;
    int lane = threadIdx.x & 31;
    const float4* h4 = (const float4*)d_h;
    float di = d_dinv[i];
    float wself = di * di;
    float4 hi = h4[(size_t)i * 32 + lane];
    float4 A0 = make_float4(wself * hi.x, wself * hi.y, wself * hi.z, wself * hi.w);
    float4 A1 = make_float4(0.f, 0.f, 0.f, 0.f);
    float4 A2 = make_float4(0.f, 0.f, 0.f, 0.f);
    float4 A3 = make_float4(0.f, 0.f, 0.f, 0.f);
    int beg = d_rowptr[i], end = d_rowptr[i + 1];
    int n = end - beg;
    int e = beg;
    int end8 = beg + (n & ~7);
    for (; e < end8; e += 8) {
        int2 p0 = d_epack[e];
        int2 p1 = d_epack[e + 1];
        int2 p2 = d_epack[e + 2];
        int2 p3 = d_epack[e + 3];
        int2 p4 = d_epack[e + 4];
        int2 p5 = d_epack[e + 5];
        int2 p6 = d_epack[e + 6];
        int2 p7 = d_epack[e + 7];
        float4 v0 = __ldg(&h4[(size_t)p0.x * 32 + lane]);
        float4 v1 = __ldg(&h4[(size_t)p1.x * 32 + lane]);
        float4 v2 = __ldg(&h4[(size_t)p2.x * 32 + lane]);
        float4 v3 = __ldg(&h4[(size_t)p3.x * 32 + lane]);
        float4 v4 = __ldg(&h4[(size_t)p4.x * 32 + lane]);
        float4 v5 = __ldg(&h4[(size_t)p5.x * 32 + lane]);
        float4 v6 = __ldg(&h4[(size_t)p6.x * 32 + lane]);
        float4 v7 = __ldg(&h4[(size_t)p7.x * 32 + lane]);
        float w0 = __int_as_float(p0.y), w1 = __int_as_float(p1.y);
        float w2 = __int_as_float(p2.y), w3 = __int_as_float(p3.y);
        float w4 = __int_as_float(p4.y), w5 = __int_as_float(p5.y);
        float w6 = __int_as_float(p6.y), w7 = __int_as_float(p7.y);
        A0.x += w0 * v0.x; A0.y += w0 * v0.y; A0.z += w0 * v0.z; A0.w += w0 * v0.w;
        A1.x += w1 * v1.x; A1.y += w1 * v1.y; A1.z += w1 * v1.z; A1.w += w1 * v1.w;
        A2.x += w2 * v2.x; A2.y += w2 * v2.y; A2.z += w2 * v2.z; A2.w += w2 * v2.w;
        A3.x += w3 * v3.x; A3.y += w3 * v3.y; A3.z += w3 * v3.z; A3.w += w3 * v3.w;
        A0.x += w4 * v4.x; A0.y += w4 * v4.y; A0.z += w4 * v4.z; A0.w += w4 * v4.w;
        A1.x += w5 * v5.x; A1.y += w5 * v5.y; A1.z += w5 * v5.z; A1.w += w5 * v5.w;
        A2.x += w6 * v6.x; A2.y += w6 * v6.y; A2.z += w6 * v6.z; A2.w += w6 * v6.w;
        A3.x += w7 * v7.x; A3.y += w7 * v7.y; A3.z += w7 * v7.z; A3.w += w7 * v7.w;
    }
    for (; e < end; e++) {
        int2 p0 = d_epack[e];
        float w0 = __int_as_float(p0.y);
        float4 v0 = __ldg(&h4[(size_t)p0.x * 32 + lane]);
        A1.x += w0 * v0.x; A1.y += w0 * v0.y; A1.z += w0 * v0.z; A1.w += w0 * v0.w;
    }
    float4 h0v = ((const float4*)d_h0)[(size_t)i * 32 + lane];
    float4 o;
    o.x = 0.9f * ((A0.x + A1.x) + (A2.x + A3.x)) + 0.1f * h0v.x;
    o.y = 0.9f * ((A0.y + A1.y) + (A2.y + A3.y)) + 0.1f * h0v.y;
    o.z = 0.9f * ((A0.z + A1.z) + (A2.z + A3.z)) + 0.1f * h0v.z;
    o.w = 0.9f * ((A0.w + A1.w) + (A2.w + A3.w)) + 0.1f * h0v.w;
    ((float4*)d_s)[(size_t)i * 32 + lane] = o;
}

// ---------------- layer GEMM + identity-map mix + ELU ----------------
// h = elu((1-beta)*s + beta*(s @ W)); double-buffered, cp.async B
__global__ __launch_bounds__(256, 2) void k_gemm_layer(const float* __restrict__ W,
                                                       float beta) {
    __shared__ float As[2][16][132];
    __shared__ float Bs[2][16][128];
    const int tid = threadIdx.x;
    const int blockRow = blockIdx.x * 128;
    const int tx = tid & 15, ty = tid >> 4;
    const int ar = tid >> 2, ac4 = tid & 3;
    const int br = tid >> 5, bc4 = tid & 31;

    float acc[8][8];
#pragma unroll
    for (int i = 0; i < 8; i++)
#pragma unroll
        for (int j = 0; j < 8; j++) acc[i][j] = 0.f;

    {
#pragma unroll
        for (int j = 0; j < 2; j++) {
            int r = ar + j * 64;
            int grow = blockRow + r;
            float4 v = make_float4(0.f, 0.f, 0.f, 0.f);
            if (grow < NN)
                v = *(const float4*)(d_s + (size_t)grow * HID + ac4 * 4);
            As[0][ac4 * 4 + 0][r] = v.x;
            As[0][ac4 * 4 + 1][r] = v.y;
            As[0][ac4 * 4 + 2][r] = v.z;
            As[0][ac4 * 4 + 3][r] = v.w;
        }
#pragma unroll
        for (int j = 0; j < 2; j++) {
            int r = br + j * 8;
            cp_async16(smem_u32(&Bs[0][r][bc4 * 4]),
                       W + (size_t)r * HID + bc4 * 4);
        }
        cp_commit();
        cp_wait0();
    }
    __syncthreads();

    int p = 0;
    for (int k0 = 0; k0 < HID; k0 += 16) {
        const int kn = k0 + 16;
        const bool more = (kn < HID);
        float4 a0n, a1n;
        if (more) {
#pragma unroll
            for (int j = 0; j < 2; j++) {
                int r = br + j * 8;
                cp_async16(smem_u32(&Bs[p ^ 1][r][bc4 * 4]),
                           W + (size_t)(kn + r) * HID + bc4 * 4);
            }
            cp_commit();
            int g0 = blockRow + ar;
            int g1 = blockRow + ar + 64;
            a0n = make_float4(0.f, 0.f, 0.f, 0.f);
            a1n = make_float4(0.f, 0.f, 0.f, 0.f);
            if (g0 < NN) a0n = *(const float4*)(d_s + (size_t)g0 * HID + kn + ac4 * 4);
            if (g1 < NN) a1n = *(const float4*)(d_s + (size_t)g1 * HID + kn + ac4 * 4);
        }
#pragma unroll
        for (int kk = 0; kk < 16; kk++) {
            float a[8], b[8];
            *(float4*)&a[0] = *(float4*)&As[p][kk][ty * 8];
            *(float4*)&a[4] = *(float4*)&As[p][kk][ty * 8 + 4];
            *(float4*)&b[0] = *(float4*)&Bs[p][kk][tx * 8];
            *(float4*)&b[4] = *(float4*)&Bs[p][kk][tx * 8 + 4];
#pragma unroll
            for (int i = 0; i < 8; i++)
#pragma unroll
                for (int j = 0; j < 8; j++)
                    acc[i][j] += a[i] * b[j];
        }
        if (more) {
            As[p ^ 1][ac4 * 4 + 0][ar] = a0n.x;
            As[p ^ 1][ac4 * 4 + 1][ar] = a0n.y;
            As[p ^ 1][ac4 * 4 + 2][ar] = a0n.z;
            As[p ^ 1][ac4 * 4 + 3][ar] = a0n.w;
            As[p ^ 1][ac4 * 4 + 0][ar + 64] = a1n.x;
            As[p ^ 1][ac4 * 4 + 1][ar + 64] = a1n.y;
            As[p ^ 1][ac4 * 4 + 2][ar + 64] = a1n.z;
            As[p ^ 1][ac4 * 4 + 3][ar + 64] = a1n.w;
            cp_wait0();
        }
        __syncthreads();
        p ^= 1;
    }

    const float omb = 1.f - beta;
#pragma unroll
    for (int i = 0; i < 8; i++) {
        int row = blockRow + ty * 8 + i;
        if (row >= NN) continue;
        const float* sp = d_s + (size_t)row * HID + tx * 8;
        float4 s0 = *(const float4*)(sp);
        float4 s1 = *(const float4*)(sp + 4);
        float sv[8] = {s0.x, s0.y, s0.z, s0.w, s1.x, s1.y, s1.z, s1.w};
        float ov[8];
#pragma unroll
        for (int j = 0; j < 8; j++) {
            float v = omb * sv[j] + beta * acc[i][j];
            ov[j] = (v > 0.f) ? v : expm1f(v);
        }
        float* hp = d_h + (size_t)row * HID + tx * 8;
        *(float4*)(hp)     = make_float4(ov[0], ov[1], ov[2], ov[3]);
        *(float4*)(hp + 4) = make_float4(ov[4], ov[5], ov[6], ov[7]);
    }
}

// ---------------- output GEMM + log_softmax (+ counter re-zero) -------------
__global__ __launch_bounds__(256) void k_out(const float* __restrict__ Wo,
                                             const float* __restrict__ Bo,
                                             float* __restrict__ out) {
    int gid = blockIdx.x * blockDim.x + threadIdx.x;
    if (gid < NN) { d_cnt[gid] = 0; d_fill[gid] = 0; }

    __shared__ float ws[128][64];   // 32 KB
    __shared__ float hs[32][128];   // 16 KB
    const int tid = threadIdx.x;
    const int base = blockIdx.x * 32;
#pragma unroll
    for (int j = 0; j < 8; j++) {
        int idx = tid + j * 256;
        int r = idx >> 4, c4 = idx & 15;
        *(float4*)&ws[r][c4 * 4] = *(const float4*)(Wo + (size_t)r * NC + c4 * 4);
    }
#pragma unroll
    for (int j = 0; j < 4; j++) {
        int idx = tid + j * 256;
        int r = idx >> 5, c4 = idx & 31;
        *(float4*)&hs[r][c4 * 4] =
            *(const float4*)(d_h + (size_t)(base + r) * HID + c4 * 4);
    }
    __syncthreads();
    const int w = tid >> 5, lane = tid & 31;
    float b0 = Bo[lane], b1 = Bo[lane + 32];
    float acc[4][2];
#pragma unroll
    for (int r = 0; r < 4; r++) { acc[r][0] = 0.f; acc[r][1] = 0.f; }
    for (int k = 0; k < HID; k++) {
        float wv0 = ws[k][lane];
        float wv1 = ws[k][lane + 32];
#pragma unroll
        for (int r = 0; r < 4; r++) {
            float hv = hs[w * 4 + r][k];
            acc[r][0] += hv * wv0;
            acc[r][1] += hv * wv1;
        }
    }
#pragma unroll
    for (int r = 0; r < 4; r++) {
        int row = base + w * 4 + r;
        float v0 = acc[r][0] + b0;
        float v1 = acc[r][1] + b1;
        float m = fmaxf(v0, v1);
#pragma unroll
        for (int off = 16; off; off >>= 1)
            m = fmaxf(m, __shfl_xor_sync(0xffffffff, m, off));
        float ssum = expf(v0 - m) + expf(v1 - m);
#pragma unroll
        for (int off = 16; off; off >>= 1)
            ssum += __shfl_xor_sync(0xffffffff, ssum, off);
        float lse = m + logf(ssum);
        out[(size_t)row * NC + lane]      = v0 - lse;
        out[(size_t)row * NC + lane + 32] = v1 - lse;
    }
}

// ---------------- launch ----------------
extern "C" void kernel_launch(void* const* d_in, const int* in_sizes, int n_in,
                              void* d_out, int out_size) {
    const float* x      = (const float*)d_in[0];
    const void*  ei     = d_in[1];
    const float* w_in   = (const float*)d_in[2];
    const float* b_in   = (const float*)d_in[3];
    const float* conv_w = (const float*)d_in[4];
    const float* w_out  = (const float*)d_in[5];
    const float* b_out  = (const float*)d_in[6];
    float*       out    = (float*)d_out;

    k_prep_edges<<<SC_BLOCKS, 256>>>(ei);                               // 0
    k_scan_dinv<<<1, 1024>>>();                                         // 1
    k_gemm_in_scatter<<<GEMM_BLOCKS + SC_BLOCKS, 256>>>(x, w_in, b_in); // 2

    for (int l = 0; l < NL; l++) {                                      // 3..18
        float beta = (float)log(0.5 / (double)(l + 1) + 1.0);
        k_agg<<<(NN + 7) / 8, 256>>>();           // slot 3 = profiled
        k_gemm_layer<<<GEMM_BLOCKS, 256>>>(conv_w + (size_t)l * HID * HID, beta);
    }

    k_out<<<NN / 32, 256>>>(w_out, b_out, out);
}

// round 10
// speedup vs baseline: 1.2198x; 1.0876x over previous
#include <cuda_runtime.h>
#include <math.h>
#include <stdint.h>
#include <mma.h>

using namespace nvcuda;

// Problem constants (GCNII_30794915512599)
#define NN   100000      // nodes
#define NE   1600000     // edges
#define FIN  512
#define HID  128
#define NC   64
#define NL   8

#define GEMM_BLOCKS ((NN + 127) / 128)          // 782
#define SC_BLOCKS   ((NE + 255) / 256)          // 6250

// wmma layer-GEMM smem geometry
#define ASTRIDE 36                               // 32 + 4 pad
#define BSTRIDE 132                              // 128 + 4 pad
#define CSTRIDE 132
#define LGEMM_SMEM (128 * CSTRIDE * 4)           // 67584 B (C overlay dominates)

// ---------------- scratch (static __device__ — no allocations) ----------------
__device__ int   d_cnt[NN];      // zero-init at load; re-zeroed by k_out each launch
__device__ int   d_fill[NN];
__device__ int   d_rowptr[NN + 1];
__device__ float d_dinv[NN];
__device__ int   d_src[NE];
__device__ int   d_dst[NE];
__device__ int2  d_epack[NE];    // packed (src, weight-as-int)
__device__ float d_h [(size_t)NN * HID];
__device__ float d_s [(size_t)NN * HID];
__device__ float d_h0[(size_t)NN * HID];

// ---------------- cp.async helpers ----------------
__device__ __forceinline__ void cp_async16(uint32_t saddr, const void* gptr) {
    asm volatile("cp.async.ca.shared.global [%0], [%1], 16;"
                 :: "r"(saddr), "l"(gptr));
}
__device__ __forceinline__ void cp_commit() {
    asm volatile("cp.async.commit_group;");
}
__device__ __forceinline__ void cp_wait0() {
    asm volatile("cp.async.wait_group 0;");
}
__device__ __forceinline__ uint32_t smem_u32(const void* p) {
    return (uint32_t)__cvta_generic_to_shared(p);
}

// ---------------- edge prep (with inline per-warp dtype detection) ----------
// edge_index is logically int64 but JAX without x64 emits int32. int32 pairs
// read as uint64 are >= 2^32 whenever the high word is nonzero; true int64
// indices are < 100000.
__global__ __launch_bounds__(256) void k_prep_edges(const void* eiv) {
    const int lane = threadIdx.x & 31;
    const unsigned long long* q = (const unsigned long long*)eiv;
    bool big = false;
#pragma unroll
    for (int k = 0; k < 2; k++) {
        int idx = (lane + k * 32) * 31;      // samples in [0, 1953]
        big |= (q[idx] > 0xFFFFFFFFull);
    }
    bool is64 = !__any_sync(0xffffffff, big);

    int e = blockIdx.x * blockDim.x + threadIdx.x;
    if (e >= NE) return;
    int s, d;
    if (is64) {
        const long long* ei = (const long long*)eiv;
        s = (int)ei[e];
        d = (int)ei[(size_t)NE + e];
    } else {
        const int* ei = (const int*)eiv;
        s = ei[e];
        d = ei[NE + e];
    }
    s = min(max(s, 0), NN - 1);
    d = min(max(d, 0), NN - 1);
    d_src[e] = s;
    d_dst[e] = d;
    atomicAdd(&d_cnt[d], 1);
}

// single-block exclusive scan over d_cnt -> d_rowptr, fused with dinv compute
__global__ __launch_bounds__(1024) void k_scan_dinv() {
    __shared__ int buf[1024];
    const int t = threadIdx.x;
    const int CH = (NN + 1023) / 1024;   // 98
    const int start = t * CH;
    int s = 0;
    for (int j = 0; j < CH; j++) {
        int idx = start + j;
        if (idx < NN) s += d_cnt[idx];
    }
    buf[t] = s;
    __syncthreads();
    for (int off = 1; off < 1024; off <<= 1) {
        int v = (t >= off) ? buf[t - off] : 0;
        __syncthreads();
        buf[t] += v;
        __syncthreads();
    }
    int run = (t == 0) ? 0 : buf[t - 1];
    for (int j = 0; j < CH; j++) {
        int idx = start + j;
        if (idx < NN) {
            int c = d_cnt[idx];
            d_rowptr[idx] = run;
            d_dinv[idx] = rsqrtf((float)(c + 1));   // +1 self loop
            run += c;
        }
    }
    if (t == 1023) d_rowptr[NN] = buf[1023];
}

// ---------------- fused: input GEMM (blocks [0,782)) + CSR scatter (rest) ----
__global__ __launch_bounds__(256, 2) void k_gemm_in_scatter(
        const float* __restrict__ X, const float* __restrict__ W,
        const float* __restrict__ B) {
    if (blockIdx.x >= GEMM_BLOCKS) {
        int e = (blockIdx.x - GEMM_BLOCKS) * 256 + threadIdx.x;
        if (e < NE) {
            int s = d_src[e], d = d_dst[e];
            int pos = d_rowptr[d] + atomicAdd(&d_fill[d], 1);
            float w = d_dinv[s] * d_dinv[d];
            d_epack[pos] = make_int2(s, __float_as_int(w));
        }
        return;
    }
    __shared__ float As[2][16][132];
    __shared__ float Bs[2][16][128];
    const int tid = threadIdx.x;
    const int blockRow = blockIdx.x * 128;
    const int tx = tid & 15, ty = tid >> 4;
    const int ar = tid >> 2, ac4 = tid & 3;
    const int br = tid >> 5, bc4 = tid & 31;

    float acc[8][8];
#pragma unroll
    for (int i = 0; i < 8; i++)
#pragma unroll
        for (int j = 0; j < 8; j++) acc[i][j] = 0.f;

    {
#pragma unroll
        for (int j = 0; j < 2; j++) {
            int r = ar + j * 64;
            int grow = blockRow + r;
            float4 v = make_float4(0.f, 0.f, 0.f, 0.f);
            if (grow < NN)
                v = *(const float4*)(X + (size_t)grow * FIN + ac4 * 4);
            As[0][ac4 * 4 + 0][r] = v.x;
            As[0][ac4 * 4 + 1][r] = v.y;
            As[0][ac4 * 4 + 2][r] = v.z;
            As[0][ac4 * 4 + 3][r] = v.w;
        }
#pragma unroll
        for (int j = 0; j < 2; j++) {
            int r = br + j * 8;
            cp_async16(smem_u32(&Bs[0][r][bc4 * 4]), W + (size_t)r * HID + bc4 * 4);
        }
        cp_commit();
        cp_wait0();
    }
    __syncthreads();

    int p = 0;
    for (int k0 = 0; k0 < FIN; k0 += 16) {
        const int kn = k0 + 16;
        const bool more = (kn < FIN);
        float4 a0n, a1n;
        if (more) {
#pragma unroll
            for (int j = 0; j < 2; j++) {
                int r = br + j * 8;
                cp_async16(smem_u32(&Bs[p ^ 1][r][bc4 * 4]),
                           W + (size_t)(kn + r) * HID + bc4 * 4);
            }
            cp_commit();
            int g0 = blockRow + ar;
            int g1 = blockRow + ar + 64;
            a0n = make_float4(0.f, 0.f, 0.f, 0.f);
            a1n = make_float4(0.f, 0.f, 0.f, 0.f);
            if (g0 < NN) a0n = *(const float4*)(X + (size_t)g0 * FIN + kn + ac4 * 4);
            if (g1 < NN) a1n = *(const float4*)(X + (size_t)g1 * FIN + kn + ac4 * 4);
        }
#pragma unroll
        for (int kk = 0; kk < 16; kk++) {
            float a[8], b[8];
            *(float4*)&a[0] = *(float4*)&As[p][kk][ty * 8];
            *(float4*)&a[4] = *(float4*)&As[p][kk][ty * 8 + 4];
            *(float4*)&b[0] = *(float4*)&Bs[p][kk][tx * 8];
            *(float4*)&b[4] = *(float4*)&Bs[p][kk][tx * 8 + 4];
#pragma unroll
            for (int i = 0; i < 8; i++)
#pragma unroll
                for (int j = 0; j < 8; j++)
                    acc[i][j] += a[i] * b[j];
        }
        if (more) {
            As[p ^ 1][ac4 * 4 + 0][ar] = a0n.x;
            As[p ^ 1][ac4 * 4 + 1][ar] = a0n.y;
            As[p ^ 1][ac4 * 4 + 2][ar] = a0n.z;
            As[p ^ 1][ac4 * 4 + 3][ar] = a0n.w;
            As[p ^ 1][ac4 * 4 + 0][ar + 64] = a1n.x;
            As[p ^ 1][ac4 * 4 + 1][ar + 64] = a1n.y;
            As[p ^ 1][ac4 * 4 + 2][ar + 64] = a1n.z;
            As[p ^ 1][ac4 * 4 + 3][ar + 64] = a1n.w;
            cp_wait0();
        }
        __syncthreads();
        p ^= 1;
    }

    float bi[8];
    *(float4*)&bi[0] = *(const float4*)(B + tx * 8);
    *(float4*)&bi[4] = *(const float4*)(B + tx * 8 + 4);
#pragma unroll
    for (int i = 0; i < 8; i++) {
        int row = blockRow + ty * 8 + i;
        if (row >= NN) continue;
        float4 o0 = make_float4(acc[i][0] + bi[0], acc[i][1] + bi[1],
                                acc[i][2] + bi[2], acc[i][3] + bi[3]);
        float4 o1 = make_float4(acc[i][4] + bi[4], acc[i][5] + bi[5],
                                acc[i][6] + bi[6], acc[i][7] + bi[7]);
        float* hp  = d_h  + (size_t)row * HID + tx * 8;
        float* h0p = d_h0 + (size_t)row * HID + tx * 8;
        *(float4*)(hp)      = o0;
        *(float4*)(hp + 4)  = o1;
        *(float4*)(h0p)     = o0;
        *(float4*)(h0p + 4) = o1;
    }
}

// ---------------- aggregation: s = 0.9*(norm-adj @ h) + 0.1*h0 ----------------
// one warp per node, float4 per lane, 8-way edge unroll (MLP=8), no smem
__global__ __launch_bounds__(256) void k_agg() {
    int i = blockIdx.x * 8 + (threadIdx.x >> 5);
    if (i >= NN) return;
    int lane = threadIdx.x & 31;
    const float4* h4 = (const float4*)d_h;
    float di = d_dinv[i];
    float wself = di * di;
    float4 hi = h4[(size_t)i * 32 + lane];
    float4 A0 = make_float4(wself * hi.x, wself * hi.y, wself * hi.z, wself * hi.w);
    float4 A1 = make_float4(0.f, 0.f, 0.f, 0.f);
    float4 A2 = make_float4(0.f, 0.f, 0.f, 0.f);
    float4 A3 = make_float4(0.f, 0.f, 0.f, 0.f);
    int beg = d_rowptr[i], end = d_rowptr[i + 1];
    int n = end - beg;
    int e = beg;
    int end8 = beg + (n & ~7);
    for (; e < end8; e += 8) {
        int2 p0 = d_epack[e];
        int2 p1 = d_epack[e + 1];
        int2 p2 = d_epack[e + 2];
        int2 p3 = d_epack[e + 3];
        int2 p4 = d_epack[e + 4];
        int2 p5 = d_epack[e + 5];
        int2 p6 = d_epack[e + 6];
        int2 p7 = d_epack[e + 7];
        float4 v0 = __ldg(&h4[(size_t)p0.x * 32 + lane]);
        float4 v1 = __ldg(&h4[(size_t)p1.x * 32 + lane]);
        float4 v2 = __ldg(&h4[(size_t)p2.x * 32 + lane]);
        float4 v3 = __ldg(&h4[(size_t)p3.x * 32 + lane]);
        float4 v4 = __ldg(&h4[(size_t)p4.x * 32 + lane]);
        float4 v5 = __ldg(&h4[(size_t)p5.x * 32 + lane]);
        float4 v6 = __ldg(&h4[(size_t)p6.x * 32 + lane]);
        float4 v7 = __ldg(&h4[(size_t)p7.x * 32 + lane]);
        float w0 = __int_as_float(p0.y), w1 = __int_as_float(p1.y);
        float w2 = __int_as_float(p2.y), w3 = __int_as_float(p3.y);
        float w4 = __int_as_float(p4.y), w5 = __int_as_float(p5.y);
        float w6 = __int_as_float(p6.y), w7 = __int_as_float(p7.y);
        A0.x += w0 * v0.x; A0.y += w0 * v0.y; A0.z += w0 * v0.z; A0.w += w0 * v0.w;
        A1.x += w1 * v1.x; A1.y += w1 * v1.y; A1.z += w1 * v1.z; A1.w += w1 * v1.w;
        A2.x += w2 * v2.x; A2.y += w2 * v2.y; A2.z += w2 * v2.z; A2.w += w2 * v2.w;
        A3.x += w3 * v3.x; A3.y += w3 * v3.y; A3.z += w3 * v3.z; A3.w += w3 * v3.w;
        A0.x += w4 * v4.x; A0.y += w4 * v4.y; A0.z += w4 * v4.z; A0.w += w4 * v4.w;
        A1.x += w5 * v5.x; A1.y += w5 * v5.y; A1.z += w5 * v5.z; A1.w += w5 * v5.w;
        A2.x += w6 * v6.x; A2.y += w6 * v6.y; A2.z += w6 * v6.z; A2.w += w6 * v6.w;
        A3.x += w7 * v7.x; A3.y += w7 * v7.y; A3.z += w7 * v7.z; A3.w += w7 * v7.w;
    }
    for (; e < end; e++) {
        int2 p0 = d_epack[e];
        float w0 = __int_as_float(p0.y);
        float4 v0 = __ldg(&h4[(size_t)p0.x * 32 + lane]);
        A1.x += w0 * v0.x; A1.y += w0 * v0.y; A1.z += w0 * v0.z; A1.w += w0 * v0.w;
    }
    float4 h0v = ((const float4*)d_h0)[(size_t)i * 32 + lane];
    float4 o;
    o.x = 0.9f * ((A0.x + A1.x) + (A2.x + A3.x)) + 0.1f * h0v.x;
    o.y = 0.9f * ((A0.y + A1.y) + (A2.y + A3.y)) + 0.1f * h0v.y;
    o.z = 0.9f * ((A0.z + A1.z) + (A2.z + A3.z)) + 0.1f * h0v.z;
    o.w = 0.9f * ((A0.w + A1.w) + (A2.w + A3.w)) + 0.1f * h0v.w;
    ((float4*)d_s)[(size_t)i * 32 + lane] = o;
}

// ---------------- layer GEMM (tf32 WMMA) + identity-map mix + ELU ----------
// h = elu((1-beta)*s + beta*(s @ W))
// 128x128 block tile, 8 warps in 2x4 grid, each warp 64x32 via m16n16k8 frags.
__global__ __launch_bounds__(256, 2) void k_gemm_layer(const float* __restrict__ W,
                                                       float beta) {
    extern __shared__ float sm[];
    float* As = sm;                      // [128][ASTRIDE]
    float* Bs = sm + 128 * ASTRIDE;      // [32][BSTRIDE]
    const int tid = threadIdx.x;
    const int blockRow = blockIdx.x * 128;
    const int warp = tid >> 5;
    const int wr = warp >> 2;            // 0..1  (row group of 64)
    const int wc = warp & 3;             // 0..3  (col group of 32)

    wmma::fragment<wmma::accumulator, 16, 16, 8, float> cf[4][2];
#pragma unroll
    for (int r = 0; r < 4; r++)
#pragma unroll
        for (int c = 0; c < 2; c++)
            wmma::fill_fragment(cf[r][c], 0.f);

    for (int k0 = 0; k0 < HID; k0 += 32) {
        // load A tile: s[blockRow..+128][k0..+32], row-major, ld=ASTRIDE
#pragma unroll
        for (int j = 0; j < 4; j++) {
            int idx = tid + j * 256;
            int r = idx >> 3, c4 = idx & 7;
            int grow = blockRow + r;
            float4 v = make_float4(0.f, 0.f, 0.f, 0.f);
            if (grow < NN)
                v = *(const float4*)(d_s + (size_t)grow * HID + k0 + c4 * 4);
            *(float4*)&As[r * ASTRIDE + c4 * 4] = v;
        }
        // load B tile: W[k0..+32][0..128], row-major, ld=BSTRIDE
#pragma unroll
        for (int j = 0; j < 4; j++) {
            int idx = tid + j * 256;
            int r = idx >> 5, c4 = idx & 31;
            *(float4*)&Bs[r * BSTRIDE + c4 * 4] =
                *(const float4*)(W + (size_t)(k0 + r) * HID + c4 * 4);
        }
        __syncthreads();
#pragma unroll
        for (int kk = 0; kk < 32; kk += 8) {
            wmma::fragment<wmma::matrix_a, 16, 16, 8, wmma::precision::tf32,
                           wmma::row_major> af[4];
            wmma::fragment<wmma::matrix_b, 16, 16, 8, wmma::precision::tf32,
                           wmma::row_major> bf[2];
#pragma unroll
            for (int r = 0; r < 4; r++) {
                wmma::load_matrix_sync(af[r],
                    &As[(wr * 64 + r * 16) * ASTRIDE + kk], ASTRIDE);
#pragma unroll
                for (int t = 0; t < af[r].num_elements; t++)
                    af[r].x[t] = wmma::__float_to_tf32(af[r].x[t]);
            }
#pragma unroll
            for (int c = 0; c < 2; c++) {
                wmma::load_matrix_sync(bf[c],
                    &Bs[kk * BSTRIDE + wc * 32 + c * 16], BSTRIDE);
#pragma unroll
                for (int t = 0; t < bf[c].num_elements; t++)
                    bf[c].x[t] = wmma::__float_to_tf32(bf[c].x[t]);
            }
#pragma unroll
            for (int r = 0; r < 4; r++)
#pragma unroll
                for (int c = 0; c < 2; c++)
                    wmma::mma_sync(cf[r][c], af[r], bf[c], cf[r][c]);
        }
        __syncthreads();
    }

    // stage C into smem (overlays As/Bs; safe after the sync above)
    float* Cs = sm;                      // [128][CSTRIDE]
#pragma unroll
    for (int r = 0; r < 4; r++)
#pragma unroll
        for (int c = 0; c < 2; c++)
            wmma::store_matrix_sync(
                &Cs[(wr * 64 + r * 16) * CSTRIDE + wc * 32 + c * 16],
                cf[r][c], CSTRIDE, wmma::mem_row_major);
    __syncthreads();

    // epilogue: mix + ELU -> d_h
    const int tx = tid & 15, ty = tid >> 4;
    const float omb = 1.f - beta;
#pragma unroll
    for (int i = 0; i < 8; i++) {
        int rl = ty * 8 + i;
        int row = blockRow + rl;
        if (row >= NN) continue;
        const float* sp = d_s + (size_t)row * HID + tx * 8;
        float4 s0 = *(const float4*)(sp);
        float4 s1 = *(const float4*)(sp + 4);
        float sv[8] = {s0.x, s0.y, s0.z, s0.w, s1.x, s1.y, s1.z, s1.w};
        float av[8];
        *(float4*)&av[0] = *(float4*)&Cs[rl * CSTRIDE + tx * 8];
        *(float4*)&av[4] = *(float4*)&Cs[rl * CSTRIDE + tx * 8 + 4];
        float ov[8];
#pragma unroll
        for (int j = 0; j < 8; j++) {
            float v = omb * sv[j] + beta * av[j];
            ov[j] = (v > 0.f) ? v : expm1f(v);
        }
        float* hp = d_h + (size_t)row * HID + tx * 8;
        *(float4*)(hp)     = make_float4(ov[0], ov[1], ov[2], ov[3]);
        *(float4*)(hp + 4) = make_float4(ov[4], ov[5], ov[6], ov[7]);
    }
}

// ---------------- output GEMM + log_softmax (+ counter re-zero) -------------
__global__ __launch_bounds__(256) void k_out(const float* __restrict__ Wo,
                                             const float* __restrict__ Bo,
                                             float* __restrict__ out) {
    int gid = blockIdx.x * blockDim.x + threadIdx.x;
    if (gid < NN) { d_cnt[gid] = 0; d_fill[gid] = 0; }

    __shared__ float ws[128][64];   // 32 KB
    __shared__ float hs[32][128];   // 16 KB
    const int tid = threadIdx.x;
    const int base = blockIdx.x * 32;
#pragma unroll
    for (int j = 0; j < 8; j++) {
        int idx = tid + j * 256;
        int r = idx >> 4, c4 = idx & 15;
        *(float4*)&ws[r][c4 * 4] = *(const float4*)(Wo + (size_t)r * NC + c4 * 4);
    }
#pragma unroll
    for (int j = 0; j < 4; j++) {
        int idx = tid + j * 256;
        int r = idx >> 5, c4 = idx & 31;
        *(float4*)&hs[r][c4 * 4] =
            *(const float4*)(d_h + (size_t)(base + r) * HID + c4 * 4);
    }
    __syncthreads();
    const int w = tid >> 5, lane = tid & 31;
    float b0 = Bo[lane], b1 = Bo[lane + 32];
    float acc[4][2];
#pragma unroll
    for (int r = 0; r < 4; r++) { acc[r][0] = 0.f; acc[r][1] = 0.f; }
    for (int k = 0; k < HID; k++) {
        float wv0 = ws[k][lane];
        float wv1 = ws[k][lane + 32];
#pragma unroll
        for (int r = 0; r < 4; r++) {
            float hv = hs[w * 4 + r][k];
            acc[r][0] += hv * wv0;
            acc[r][1] += hv * wv1;
        }
    }
#pragma unroll
    for (int r = 0; r < 4; r++) {
        int row = base + w * 4 + r;
        float v0 = acc[r][0] + b0;
        float v1 = acc[r][1] + b1;
        float m = fmaxf(v0, v1);
#pragma unroll
        for (int off = 16; off; off >>= 1)
            m = fmaxf(m, __shfl_xor_sync(0xffffffff, m, off));
        float ssum = expf(v0 - m) + expf(v1 - m);
#pragma unroll
        for (int off = 16; off; off >>= 1)
            ssum += __shfl_xor_sync(0xffffffff, ssum, off);
        float lse = m + logf(ssum);
        out[(size_t)row * NC + lane]      = v0 - lse;
        out[(size_t)row * NC + lane + 32] = v1 - lse;
    }
}

// ---------------- launch ----------------
extern "C" void kernel_launch(void* const* d_in, const int* in_sizes, int n_in,
                              void* d_out, int out_size) {
    const float* x      = (const float*)d_in[0];
    const void*  ei     = d_in[1];
    const float* w_in   = (const float*)d_in[2];
    const float* b_in   = (const float*)d_in[3];
    const float* conv_w = (const float*)d_in[4];
    const float* w_out  = (const float*)d_in[5];
    const float* b_out  = (const float*)d_in[6];
    float*       out    = (float*)d_out;

    cudaFuncSetAttribute(k_gemm_layer,
                         cudaFuncAttributeMaxDynamicSharedMemorySize, LGEMM_SMEM);

    k_prep_edges<<<SC_BLOCKS, 256>>>(ei);                               // 0
    k_scan_dinv<<<1, 1024>>>();                                         // 1
    k_gemm_in_scatter<<<GEMM_BLOCKS + SC_BLOCKS, 256>>>(x, w_in, b_in); // 2

    for (int l = 0; l < NL; l++) {                                      // 3..18
        float beta = (float)log(0.5 / (double)(l + 1) + 1.0);
        k_agg<<<(NN + 7) / 8, 256>>>();           // slot 3 = profiled
        k_gemm_layer<<<GEMM_BLOCKS, 256, LGEMM_SMEM>>>(
            conv_w + (size_t)l * HID * HID, beta);
    }

    k_out<<<NN / 32, 256>>>(w_out, b_out, out);
}

// round 11
// speedup vs baseline: 1.2778x; 1.0476x over previous
#include <cuda_runtime.h>
#include <math.h>
#include <stdint.h>
#include <mma.h>

using namespace nvcuda;

// Problem constants (GCNII_30794915512599)
#define NN   100000      // nodes
#define NE   1600000     // edges
#define FIN  512
#define HID  128
#define NC   64
#define NL   8

#define GEMM_BLOCKS ((NN + 127) / 128)          // 782
#define SC_BLOCKS   ((NE + 255) / 256)          // 6250

// wmma layer-GEMM smem geometry
#define ASTRIDE 36                               // 32 + 4 pad
#define BSTRIDE 132                              // 128 + 4 pad
#define CSTRIDE 132
#define LGEMM_SMEM (128 * CSTRIDE * 4)           // 67584 B

// tf32 input-GEMM smem: As[2][128][36] + Bs[2][32][132]; C overlays
#define IN_AS_STAGE (128 * ASTRIDE)              // floats
#define IN_BS_STAGE (32 * BSTRIDE)
#define IN_SMEM_FLOATS (2 * IN_AS_STAGE + 2 * IN_BS_STAGE)   // 17664
#define INGEMM_SMEM (IN_SMEM_FLOATS * 4)         // 70656 B (> C overlay 67584)

// ---------------- scratch (static __device__ — no allocations) ----------------
__device__ int   d_cnt[NN];      // zero-init at load; re-zeroed by k_out each launch
__device__ int   d_fill[NN];
__device__ int   d_rowptr[NN + 1];
__device__ float d_dinv[NN];
__device__ int   d_src[NE];
__device__ int   d_dst[NE];
__device__ int2  d_epack[NE];    // packed (src, weight-as-int)
__device__ float d_h [(size_t)NN * HID];
__device__ float d_s [(size_t)NN * HID];
__device__ float d_h0[(size_t)NN * HID];

// ---------------- cp.async helpers ----------------
__device__ __forceinline__ void cp_async16(uint32_t saddr, const void* gptr) {
    asm volatile("cp.async.ca.shared.global [%0], [%1], 16;"
                 :: "r"(saddr), "l"(gptr));
}
__device__ __forceinline__ void cp_commit() {
    asm volatile("cp.async.commit_group;");
}
__device__ __forceinline__ void cp_wait0() {
    asm volatile("cp.async.wait_group 0;");
}
__device__ __forceinline__ uint32_t smem_u32(const void* p) {
    return (uint32_t)__cvta_generic_to_shared(p);
}

// ---------------- edge prep (with inline per-warp dtype detection) ----------
// edge_index is logically int64 but JAX without x64 emits int32. int32 pairs
// read as uint64 are >= 2^32 whenever the high word is nonzero; true int64
// indices are < 100000.
__global__ __launch_bounds__(256) void k_prep_edges(const void* eiv) {
    const int lane = threadIdx.x & 31;
    const unsigned long long* q = (const unsigned long long*)eiv;
    bool big = false;
#pragma unroll
    for (int k = 0; k < 2; k++) {
        int idx = (lane + k * 32) * 31;      // samples in [0, 1953]
        big |= (q[idx] > 0xFFFFFFFFull);
    }
    bool is64 = !__any_sync(0xffffffff, big);

    int e = blockIdx.x * blockDim.x + threadIdx.x;
    if (e >= NE) return;
    int s, d;
    if (is64) {
        const long long* ei = (const long long*)eiv;
        s = (int)ei[e];
        d = (int)ei[(size_t)NE + e];
    } else {
        const int* ei = (const int*)eiv;
        s = ei[e];
        d = ei[NE + e];
    }
    s = min(max(s, 0), NN - 1);
    d = min(max(d, 0), NN - 1);
    d_src[e] = s;
    d_dst[e] = d;
    atomicAdd(&d_cnt[d], 1);
}

// single-block exclusive scan over d_cnt -> d_rowptr, fused with dinv compute
__global__ __launch_bounds__(1024) void k_scan_dinv() {
    __shared__ int buf[1024];
    const int t = threadIdx.x;
    const int CH = (NN + 1023) / 1024;   // 98
    const int start = t * CH;
    int s = 0;
    for (int j = 0; j < CH; j++) {
        int idx = start + j;
        if (idx < NN) s += d_cnt[idx];
    }
    buf[t] = s;
    __syncthreads();
    for (int off = 1; off < 1024; off <<= 1) {
        int v = (t >= off) ? buf[t - off] : 0;
        __syncthreads();
        buf[t] += v;
        __syncthreads();
    }
    int run = (t == 0) ? 0 : buf[t - 1];
    for (int j = 0; j < CH; j++) {
        int idx = start + j;
        if (idx < NN) {
            int c = d_cnt[idx];
            d_rowptr[idx] = run;
            d_dinv[idx] = rsqrtf((float)(c + 1));   // +1 self loop
            run += c;
        }
    }
    if (t == 1023) d_rowptr[NN] = buf[1023];
}

// ---------------- fused: tf32 input GEMM (blocks [0,782)) + scatter (rest) --
// gemm: h = x @ w_in + b_in ; h0 = h. 128x128 tile, K=512 in 16 chunks of 32,
// cp.async double-buffered A and B, 8 warps 2x4, each 64x32 via m16n16k8.
__global__ __launch_bounds__(256, 2) void k_gemm_in_scatter(
        const float* __restrict__ X, const float* __restrict__ W,
        const float* __restrict__ B) {
    if (blockIdx.x >= GEMM_BLOCKS) {
        int e = (blockIdx.x - GEMM_BLOCKS) * 256 + threadIdx.x;
        if (e < NE) {
            int s = d_src[e], d = d_dst[e];
            int pos = d_rowptr[d] + atomicAdd(&d_fill[d], 1);
            float w = d_dinv[s] * d_dinv[d];
            d_epack[pos] = make_int2(s, __float_as_int(w));
        }
        return;
    }
    extern __shared__ float sm[];
    float* As[2] = { sm, sm + IN_AS_STAGE };
    float* Bs[2] = { sm + 2 * IN_AS_STAGE, sm + 2 * IN_AS_STAGE + IN_BS_STAGE };
    const int tid = threadIdx.x;
    const int blockRow = blockIdx.x * 128;
    const int warp = tid >> 5;
    const int wr = warp >> 2;            // 0..1
    const int wc = warp & 3;             // 0..3

    // loader coords: A chunks (row, chunk-of-8), B chunks (krow, chunk-of-32)
    const int ar = tid >> 1, ac = tid & 1;       // 128 rows x 2 base chunks
    const int brr = tid >> 3, bcc = tid & 7;     // 32 rows x 8 base chunks

    wmma::fragment<wmma::accumulator, 16, 16, 8, float> cf[4][2];
#pragma unroll
    for (int r = 0; r < 4; r++)
#pragma unroll
        for (int c = 0; c < 2; c++)
            wmma::fill_fragment(cf[r][c], 0.f);

    // clamped source row (garbage lands only in C rows the epilogue skips)
    const int asrc0 = min(blockRow + ar, NN - 1);

    // stage issue: A 128x32 (8 chunks/row; threads cover 2 each, x4), B 32x128
    auto issue_stage = [&](int buf, int k0) {
#pragma unroll
        for (int j = 0; j < 4; j++) {
            int c = ac + j * 2;          // chunk 0..7
            cp_async16(smem_u32(&As[buf][ar * ASTRIDE + c * 4]),
                       X + (size_t)asrc0 * FIN + k0 + c * 4);
        }
#pragma unroll
        for (int j = 0; j < 4; j++) {
            int c = bcc + j * 8;         // chunk 0..31
            cp_async16(smem_u32(&Bs[buf][brr * BSTRIDE + c * 4]),
                       W + (size_t)(k0 + brr) * HID + c * 4);
        }
        cp_commit();
    };

    issue_stage(0, 0);
    int p = 0;
    for (int s = 0; s < FIN / 32; s++) {
        cp_wait0();
        __syncthreads();
        if (s + 1 < FIN / 32) issue_stage(p ^ 1, (s + 1) * 32);
#pragma unroll
        for (int kk = 0; kk < 32; kk += 8) {
            wmma::fragment<wmma::matrix_a, 16, 16, 8, wmma::precision::tf32,
                           wmma::row_major> af[4];
            wmma::fragment<wmma::matrix_b, 16, 16, 8, wmma::precision::tf32,
                           wmma::row_major> bf[2];
#pragma unroll
            for (int r = 0; r < 4; r++) {
                wmma::load_matrix_sync(af[r],
                    &As[p][(wr * 64 + r * 16) * ASTRIDE + kk], ASTRIDE);
#pragma unroll
                for (int t = 0; t < af[r].num_elements; t++)
                    af[r].x[t] = wmma::__float_to_tf32(af[r].x[t]);
            }
#pragma unroll
            for (int c = 0; c < 2; c++) {
                wmma::load_matrix_sync(bf[c],
                    &Bs[p][kk * BSTRIDE + wc * 32 + c * 16], BSTRIDE);
#pragma unroll
                for (int t = 0; t < bf[c].num_elements; t++)
                    bf[c].x[t] = wmma::__float_to_tf32(bf[c].x[t]);
            }
#pragma unroll
            for (int r = 0; r < 4; r++)
#pragma unroll
                for (int c = 0; c < 2; c++)
                    wmma::mma_sync(cf[r][c], af[r], bf[c], cf[r][c]);
        }
        p ^= 1;
    }
    __syncthreads();

    // stage C into smem overlay
    float* Cs = sm;                      // [128][CSTRIDE]
#pragma unroll
    for (int r = 0; r < 4; r++)
#pragma unroll
        for (int c = 0; c < 2; c++)
            wmma::store_matrix_sync(
                &Cs[(wr * 64 + r * 16) * CSTRIDE + wc * 32 + c * 16],
                cf[r][c], CSTRIDE, wmma::mem_row_major);
    __syncthreads();

    // epilogue: + bias -> d_h and d_h0
    const int tx = tid & 15, ty = tid >> 4;
    float bi[8];
    *(float4*)&bi[0] = *(const float4*)(B + tx * 8);
    *(float4*)&bi[4] = *(const float4*)(B + tx * 8 + 4);
#pragma unroll
    for (int i = 0; i < 8; i++) {
        int rl = ty * 8 + i;
        int row = blockRow + rl;
        if (row >= NN) continue;
        float av[8];
        *(float4*)&av[0] = *(float4*)&Cs[rl * CSTRIDE + tx * 8];
        *(float4*)&av[4] = *(float4*)&Cs[rl * CSTRIDE + tx * 8 + 4];
        float4 o0 = make_float4(av[0] + bi[0], av[1] + bi[1],
                                av[2] + bi[2], av[3] + bi[3]);
        float4 o1 = make_float4(av[4] + bi[4], av[5] + bi[5],
                                av[6] + bi[6], av[7] + bi[7]);
        float* hp  = d_h  + (size_t)row * HID + tx * 8;
        float* h0p = d_h0 + (size_t)row * HID + tx * 8;
        *(float4*)(hp)      = o0;
        *(float4*)(hp + 4)  = o1;
        *(float4*)(h0p)     = o0;
        *(float4*)(h0p + 4) = o1;
    }
}

// ---------------- aggregation: s = 0.9*(norm-adj @ h) + 0.1*h0 ----------------
// one warp per node, float4 per lane, 8-way edge unroll (MLP=8), no smem
__global__ __launch_bounds__(256) void k_agg() {
    int i = blockIdx.x * 8 + (threadIdx.x >> 5);
    if (i >= NN) return;
    int lane = threadIdx.x & 31;
    const float4* h4 = (const float4*)d_h;
    float di = d_dinv[i];
    float wself = di * di;
    float4 hi = h4[(size_t)i * 32 + lane];
    float4 A0 = make_float4(wself * hi.x, wself * hi.y, wself * hi.z, wself * hi.w);
    float4 A1 = make_float4(0.f, 0.f, 0.f, 0.f);
    float4 A2 = make_float4(0.f, 0.f, 0.f, 0.f);
    float4 A3 = make_float4(0.f, 0.f, 0.f, 0.f);
    int beg = d_rowptr[i], end = d_rowptr[i + 1];
    int n = end - beg;
    int e = beg;
    int end8 = beg + (n & ~7);
    for (; e < end8; e += 8) {
        int2 p0 = d_epack[e];
        int2 p1 = d_epack[e + 1];
        int2 p2 = d_epack[e + 2];
        int2 p3 = d_epack[e + 3];
        int2 p4 = d_epack[e + 4];
        int2 p5 = d_epack[e + 5];
        int2 p6 = d_epack[e + 6];
        int2 p7 = d_epack[e + 7];
        float4 v0 = __ldg(&h4[(size_t)p0.x * 32 + lane]);
        float4 v1 = __ldg(&h4[(size_t)p1.x * 32 + lane]);
        float4 v2 = __ldg(&h4[(size_t)p2.x * 32 + lane]);
        float4 v3 = __ldg(&h4[(size_t)p3.x * 32 + lane]);
        float4 v4 = __ldg(&h4[(size_t)p4.x * 32 + lane]);
        float4 v5 = __ldg(&h4[(size_t)p5.x * 32 + lane]);
        float4 v6 = __ldg(&h4[(size_t)p6.x * 32 + lane]);
        float4 v7 = __ldg(&h4[(size_t)p7.x * 32 + lane]);
        float w0 = __int_as_float(p0.y), w1 = __int_as_float(p1.y);
        float w2 = __int_as_float(p2.y), w3 = __int_as_float(p3.y);
        float w4 = __int_as_float(p4.y), w5 = __int_as_float(p5.y);
        float w6 = __int_as_float(p6.y), w7 = __int_as_float(p7.y);
        A0.x += w0 * v0.x; A0.y += w0 * v0.y; A0.z += w0 * v0.z; A0.w += w0 * v0.w;
        A1.x += w1 * v1.x; A1.y += w1 * v1.y; A1.z += w1 * v1.z; A1.w += w1 * v1.w;
        A2.x += w2 * v2.x; A2.y += w2 * v2.y; A2.z += w2 * v2.z; A2.w += w2 * v2.w;
        A3.x += w3 * v3.x; A3.y += w3 * v3.y; A3.z += w3 * v3.z; A3.w += w3 * v3.w;
        A0.x += w4 * v4.x; A0.y += w4 * v4.y; A0.z += w4 * v4.z; A0.w += w4 * v4.w;
        A1.x += w5 * v5.x; A1.y += w5 * v5.y; A1.z += w5 * v5.z; A1.w += w5 * v5.w;
        A2.x += w6 * v6.x; A2.y += w6 * v6.y; A2.z += w6 * v6.z; A2.w += w6 * v6.w;
        A3.x += w7 * v7.x; A3.y += w7 * v7.y; A3.z += w7 * v7.z; A3.w += w7 * v7.w;
    }
    for (; e < end; e++) {
        int2 p0 = d_epack[e];
        float w0 = __int_as_float(p0.y);
        float4 v0 = __ldg(&h4[(size_t)p0.x * 32 + lane]);
        A1.x += w0 * v0.x; A1.y += w0 * v0.y; A1.z += w0 * v0.z; A1.w += w0 * v0.w;
    }
    float4 h0v = ((const float4*)d_h0)[(size_t)i * 32 + lane];
    float4 o;
    o.x = 0.9f * ((A0.x + A1.x) + (A2.x + A3.x)) + 0.1f * h0v.x;
    o.y = 0.9f * ((A0.y + A1.y) + (A2.y + A3.y)) + 0.1f * h0v.y;
    o.z = 0.9f * ((A0.z + A1.z) + (A2.z + A3.z)) + 0.1f * h0v.z;
    o.w = 0.9f * ((A0.w + A1.w) + (A2.w + A3.w)) + 0.1f * h0v.w;
    ((float4*)d_s)[(size_t)i * 32 + lane] = o;
}

// ---------------- layer GEMM (tf32 WMMA) + identity-map mix + ELU ----------
// h = elu((1-beta)*s + beta*(s @ W))
__global__ __launch_bounds__(256, 2) void k_gemm_layer(const float* __restrict__ W,
                                                       float beta) {
    extern __shared__ float sm[];
    float* As = sm;                      // [128][ASTRIDE]
    float* Bs = sm + 128 * ASTRIDE;      // [32][BSTRIDE]
    const int tid = threadIdx.x;
    const int blockRow = blockIdx.x * 128;
    const int warp = tid >> 5;
    const int wr = warp >> 2;
    const int wc = warp & 3;

    wmma::fragment<wmma::accumulator, 16, 16, 8, float> cf[4][2];
#pragma unroll
    for (int r = 0; r < 4; r++)
#pragma unroll
        for (int c = 0; c < 2; c++)
            wmma::fill_fragment(cf[r][c], 0.f);

    for (int k0 = 0; k0 < HID; k0 += 32) {
#pragma unroll
        for (int j = 0; j < 4; j++) {
            int idx = tid + j * 256;
            int r = idx >> 3, c4 = idx & 7;
            int grow = blockRow + r;
            float4 v = make_float4(0.f, 0.f, 0.f, 0.f);
            if (grow < NN)
                v = *(const float4*)(d_s + (size_t)grow * HID + k0 + c4 * 4);
            *(float4*)&As[r * ASTRIDE + c4 * 4] = v;
        }
#pragma unroll
        for (int j = 0; j < 4; j++) {
            int idx = tid + j * 256;
            int r = idx >> 5, c4 = idx & 31;
            *(float4*)&Bs[r * BSTRIDE + c4 * 4] =
                *(const float4*)(W + (size_t)(k0 + r) * HID + c4 * 4);
        }
        __syncthreads();
#pragma unroll
        for (int kk = 0; kk < 32; kk += 8) {
            wmma::fragment<wmma::matrix_a, 16, 16, 8, wmma::precision::tf32,
                           wmma::row_major> af[4];
            wmma::fragment<wmma::matrix_b, 16, 16, 8, wmma::precision::tf32,
                           wmma::row_major> bf[2];
#pragma unroll
            for (int r = 0; r < 4; r++) {
                wmma::load_matrix_sync(af[r],
                    &As[(wr * 64 + r * 16) * ASTRIDE + kk], ASTRIDE);
#pragma unroll
                for (int t = 0; t < af[r].num_elements; t++)
                    af[r].x[t] = wmma::__float_to_tf32(af[r].x[t]);
            }
#pragma unroll
            for (int c = 0; c < 2; c++) {
                wmma::load_matrix_sync(bf[c],
                    &Bs[kk * BSTRIDE + wc * 32 + c * 16], BSTRIDE);
#pragma unroll
                for (int t = 0; t < bf[c].num_elements; t++)
                    bf[c].x[t] = wmma::__float_to_tf32(bf[c].x[t]);
            }
#pragma unroll
            for (int r = 0; r < 4; r++)
#pragma unroll
                for (int c = 0; c < 2; c++)
                    wmma::mma_sync(cf[r][c], af[r], bf[c], cf[r][c]);
        }
        __syncthreads();
    }

    float* Cs = sm;                      // [128][CSTRIDE]
#pragma unroll
    for (int r = 0; r < 4; r++)
#pragma unroll
        for (int c = 0; c < 2; c++)
            wmma::store_matrix_sync(
                &Cs[(wr * 64 + r * 16) * CSTRIDE + wc * 32 + c * 16],
                cf[r][c], CSTRIDE, wmma::mem_row_major);
    __syncthreads();

    const int tx = tid & 15, ty = tid >> 4;
    const float omb = 1.f - beta;
#pragma unroll
    for (int i = 0; i < 8; i++) {
        int rl = ty * 8 + i;
        int row = blockRow + rl;
        if (row >= NN) continue;
        const float* sp = d_s + (size_t)row * HID + tx * 8;
        float4 s0 = *(const float4*)(sp);
        float4 s1 = *(const float4*)(sp + 4);
        float sv[8] = {s0.x, s0.y, s0.z, s0.w, s1.x, s1.y, s1.z, s1.w};
        float av[8];
        *(float4*)&av[0] = *(float4*)&Cs[rl * CSTRIDE + tx * 8];
        *(float4*)&av[4] = *(float4*)&Cs[rl * CSTRIDE + tx * 8 + 4];
        float ov[8];
#pragma unroll
        for (int j = 0; j < 8; j++) {
            float v = omb * sv[j] + beta * av[j];
            ov[j] = (v > 0.f) ? v : expm1f(v);
        }
        float* hp = d_h + (size_t)row * HID + tx * 8;
        *(float4*)(hp)     = make_float4(ov[0], ov[1], ov[2], ov[3]);
        *(float4*)(hp + 4) = make_float4(ov[4], ov[5], ov[6], ov[7]);
    }
}

// ---------------- output GEMM + log_softmax (+ counter re-zero) -------------
__global__ __launch_bounds__(256) void k_out(const float* __restrict__ Wo,
                                             const float* __restrict__ Bo,
                                             float* __restrict__ out) {
    int gid = blockIdx.x * blockDim.x + threadIdx.x;
    if (gid < NN) { d_cnt[gid] = 0; d_fill[gid] = 0; }

    __shared__ float ws[128][64];   // 32 KB
    __shared__ float hs[32][128];   // 16 KB
    const int tid = threadIdx.x;
    const int base = blockIdx.x * 32;
#pragma unroll
    for (int j = 0; j < 8; j++) {
        int idx = tid + j * 256;
        int r = idx >> 4, c4 = idx & 15;
        *(float4*)&ws[r][c4 * 4] = *(const float4*)(Wo + (size_t)r * NC + c4 * 4);
    }
#pragma unroll
    for (int j = 0; j < 4; j++) {
        int idx = tid + j * 256;
        int r = idx >> 5, c4 = idx & 31;
        *(float4*)&hs[r][c4 * 4] =
            *(const float4*)(d_h + (size_t)(base + r) * HID + c4 * 4);
    }
    __syncthreads();
    const int w = tid >> 5, lane = tid & 31;
    float b0 = Bo[lane], b1 = Bo[lane + 32];
    float acc[4][2];
#pragma unroll
    for (int r = 0; r < 4; r++) { acc[r][0] = 0.f; acc[r][1] = 0.f; }
    for (int k = 0; k < HID; k++) {
        float wv0 = ws[k][lane];
        float wv1 = ws[k][lane + 32];
#pragma unroll
        for (int r = 0; r < 4; r++) {
            float hv = hs[w * 4 + r][k];
            acc[r][0] += hv * wv0;
            acc[r][1] += hv * wv1;
        }
    }
#pragma unroll
    for (int r = 0; r < 4; r++) {
        int row = base + w * 4 + r;
        float v0 = acc[r][0] + b0;
        float v1 = acc[r][1] + b1;
        float m = fmaxf(v0, v1);
#pragma unroll
        for (int off = 16; off; off >>= 1)
            m = fmaxf(m, __shfl_xor_sync(0xffffffff, m, off));
        float ssum = expf(v0 - m) + expf(v1 - m);
#pragma unroll
        for (int off = 16; off; off >>= 1)
            ssum += __shfl_xor_sync(0xffffffff, ssum, off);
        float lse = m + logf(ssum);
        out[(size_t)row * NC + lane]      = v0 - lse;
        out[(size_t)row * NC + lane + 32] = v1 - lse;
    }
}

// ---------------- launch ----------------
extern "C" void kernel_launch(void* const* d_in, const int* in_sizes, int n_in,
                              void* d_out, int out_size) {
    const float* x      = (const float*)d_in[0];
    const void*  ei     = d_in[1];
    const float* w_in   = (const float*)d_in[2];
    const float* b_in   = (const float*)d_in[3];
    const float* conv_w = (const float*)d_in[4];
    const float* w_out  = (const float*)d_in[5];
    const float* b_out  = (const float*)d_in[6];
    float*       out    = (float*)d_out;

    cudaFuncSetAttribute(k_gemm_in_scatter,
                         cudaFuncAttributeMaxDynamicSharedMemorySize, INGEMM_SMEM);
    cudaFuncSetAttribute(k_gemm_layer,
                         cudaFuncAttributeMaxDynamicSharedMemorySize, LGEMM_SMEM);

    k_prep_edges<<<SC_BLOCKS, 256>>>(ei);                               // 0
    k_scan_dinv<<<1, 1024>>>();                                         // 1
    k_gemm_in_scatter<<<GEMM_BLOCKS + SC_BLOCKS, 256, INGEMM_SMEM>>>(
        x, w_in, b_in);                                                 // 2

    for (int l = 0; l < NL; l++) {                                      // 3..18
        float beta = (float)log(0.5 / (double)(l + 1) + 1.0);
        k_agg<<<(NN + 7) / 8, 256>>>();           // slot 3 = profiled
        k_gemm_layer<<<GEMM_BLOCKS, 256, LGEMM_SMEM>>>(
            conv_w + (size_t)l * HID * HID, beta);
    }

    k_out<<<NN / 32, 256>>>(w_out, b_out, out);
}

// round 12
// speedup vs baseline: 1.2889x; 1.0087x over previous
#include <cuda_runtime.h>
#include <cuda_fp16.h>
#include <math.h>
#include <stdint.h>
#include <mma.h>

using namespace nvcuda;

// Problem constants (GCNII_30794915512599)
#define NN   100000      // nodes
#define NE   1600000     // edges
#define FIN  512
#define HID  128
#define NC   64
#define NL   8

#define GEMM_BLOCKS ((NN + 127) / 128)          // 782
#define SC_BLOCKS   ((NE + 255) / 256)          // 6250

// wmma layer-GEMM smem geometry
#define ASTRIDE 36                               // 32 + 4 pad
#define BSTRIDE 132                              // 128 + 4 pad
#define CSTRIDE 132
#define LGEMM_SMEM (128 * CSTRIDE * 4)           // 67584 B

// tf32 input-GEMM smem: As[2][128][36] + Bs[2][32][132]; C overlays
#define IN_AS_STAGE (128 * ASTRIDE)              // floats
#define IN_BS_STAGE (32 * BSTRIDE)
#define IN_SMEM_FLOATS (2 * IN_AS_STAGE + 2 * IN_BS_STAGE)   // 17664
#define INGEMM_SMEM (IN_SMEM_FLOATS * 4)         // 70656 B

// ---------------- scratch (static __device__ — no allocations) ----------------
__device__ int    d_cnt[NN];     // zero-init at load; re-zeroed by k_out each launch
__device__ int    d_fill[NN];
__device__ int    d_rowptr[NN + 1];
__device__ float  d_dinv[NN];
__device__ int    d_src[NE];
__device__ int    d_dst[NE];
__device__ int2   d_epack[NE];   // packed (src, weight-as-int)
__device__ float  d_h [(size_t)NN * HID];
__device__ __half d_h16[(size_t)NN * HID];   // fp16 gather mirror of h
__device__ float  d_s [(size_t)NN * HID];
__device__ float  d_h0[(size_t)NN * HID];

// ---------------- cp.async helpers ----------------
__device__ __forceinline__ void cp_async16(uint32_t saddr, const void* gptr) {
    asm volatile("cp.async.ca.shared.global [%0], [%1], 16;"
                 :: "r"(saddr), "l"(gptr));
}
__device__ __forceinline__ void cp_commit() {
    asm volatile("cp.async.commit_group;");
}
__device__ __forceinline__ void cp_wait0() {
    asm volatile("cp.async.wait_group 0;");
}
__device__ __forceinline__ uint32_t smem_u32(const void* p) {
    return (uint32_t)__cvta_generic_to_shared(p);
}

// pack 8 floats -> 8 halfs (16B)
__device__ __forceinline__ uint4 pack_half8(const float* v) {
    __half2 q0 = __floats2half2_rn(v[0], v[1]);
    __half2 q1 = __floats2half2_rn(v[2], v[3]);
    __half2 q2 = __floats2half2_rn(v[4], v[5]);
    __half2 q3 = __floats2half2_rn(v[6], v[7]);
    uint4 u;
    u.x = *(uint32_t*)&q0; u.y = *(uint32_t*)&q1;
    u.z = *(uint32_t*)&q2; u.w = *(uint32_t*)&q3;
    return u;
}

// ---------------- edge prep (with inline per-warp dtype detection) ----------
// edge_index is logically int64 but JAX without x64 emits int32. int32 pairs
// read as uint64 are >= 2^32 whenever the high word is nonzero; true int64
// indices are < 100000.
__global__ __launch_bounds__(256) void k_prep_edges(const void* eiv) {
    const int lane = threadIdx.x & 31;
    const unsigned long long* q = (const unsigned long long*)eiv;
    bool big = false;
#pragma unroll
    for (int k = 0; k < 2; k++) {
        int idx = (lane + k * 32) * 31;      // samples in [0, 1953]
        big |= (q[idx] > 0xFFFFFFFFull);
    }
    bool is64 = !__any_sync(0xffffffff, big);

    int e = blockIdx.x * blockDim.x + threadIdx.x;
    if (e >= NE) return;
    int s, d;
    if (is64) {
        const long long* ei = (const long long*)eiv;
        s = (int)ei[e];
        d = (int)ei[(size_t)NE + e];
    } else {
        const int* ei = (const int*)eiv;
        s = ei[e];
        d = ei[NE + e];
    }
    s = min(max(s, 0), NN - 1);
    d = min(max(d, 0), NN - 1);
    d_src[e] = s;
    d_dst[e] = d;
    atomicAdd(&d_cnt[d], 1);
}

// single-block exclusive scan over d_cnt -> d_rowptr, fused with dinv compute
__global__ __launch_bounds__(1024) void k_scan_dinv() {
    __shared__ int buf[1024];
    const int t = threadIdx.x;
    const int CH = (NN + 1023) / 1024;   // 98
    const int start = t * CH;
    int s = 0;
    for (int j = 0; j < CH; j++) {
        int idx = start + j;
        if (idx < NN) s += d_cnt[idx];
    }
    buf[t] = s;
    __syncthreads();
    for (int off = 1; off < 1024; off <<= 1) {
        int v = (t >= off) ? buf[t - off] : 0;
        __syncthreads();
        buf[t] += v;
        __syncthreads();
    }
    int run = (t == 0) ? 0 : buf[t - 1];
    for (int j = 0; j < CH; j++) {
        int idx = start + j;
        if (idx < NN) {
            int c = d_cnt[idx];
            d_rowptr[idx] = run;
            d_dinv[idx] = rsqrtf((float)(c + 1));   // +1 self loop
            run += c;
        }
    }
    if (t == 1023) d_rowptr[NN] = buf[1023];
}

// ---------------- fused: tf32 input GEMM (blocks [0,782)) + scatter (rest) --
// gemm: h = x @ w_in + b_in ; h0 = h ; h16 = fp16(h)
__global__ __launch_bounds__(256, 2) void k_gemm_in_scatter(
        const float* __restrict__ X, const float* __restrict__ W,
        const float* __restrict__ B) {
    if (blockIdx.x >= GEMM_BLOCKS) {
        int e = (blockIdx.x - GEMM_BLOCKS) * 256 + threadIdx.x;
        if (e < NE) {
            int s = d_src[e], d = d_dst[e];
            int pos = d_rowptr[d] + atomicAdd(&d_fill[d], 1);
            float w = d_dinv[s] * d_dinv[d];
            d_epack[pos] = make_int2(s, __float_as_int(w));
        }
        return;
    }
    extern __shared__ float sm[];
    float* As[2] = { sm, sm + IN_AS_STAGE };
    float* Bs[2] = { sm + 2 * IN_AS_STAGE, sm + 2 * IN_AS_STAGE + IN_BS_STAGE };
    const int tid = threadIdx.x;
    const int blockRow = blockIdx.x * 128;
    const int warp = tid >> 5;
    const int wr = warp >> 2;            // 0..1
    const int wc = warp & 3;             // 0..3

    const int ar = tid >> 1, ac = tid & 1;
    const int brr = tid >> 3, bcc = tid & 7;

    wmma::fragment<wmma::accumulator, 16, 16, 8, float> cf[4][2];
#pragma unroll
    for (int r = 0; r < 4; r++)
#pragma unroll
        for (int c = 0; c < 2; c++)
            wmma::fill_fragment(cf[r][c], 0.f);

    const int asrc0 = min(blockRow + ar, NN - 1);

    auto issue_stage = [&](int buf, int k0) {
#pragma unroll
        for (int j = 0; j < 4; j++) {
            int c = ac + j * 2;
            cp_async16(smem_u32(&As[buf][ar * ASTRIDE + c * 4]),
                       X + (size_t)asrc0 * FIN + k0 + c * 4);
        }
#pragma unroll
        for (int j = 0; j < 4; j++) {
            int c = bcc + j * 8;
            cp_async16(smem_u32(&Bs[buf][brr * BSTRIDE + c * 4]),
                       W + (size_t)(k0 + brr) * HID + c * 4);
        }
        cp_commit();
    };

    issue_stage(0, 0);
    int p = 0;
    for (int s = 0; s < FIN / 32; s++) {
        cp_wait0();
        __syncthreads();
        if (s + 1 < FIN / 32) issue_stage(p ^ 1, (s + 1) * 32);
#pragma unroll
        for (int kk = 0; kk < 32; kk += 8) {
            wmma::fragment<wmma::matrix_a, 16, 16, 8, wmma::precision::tf32,
                           wmma::row_major> af[4];
            wmma::fragment<wmma::matrix_b, 16, 16, 8, wmma::precision::tf32,
                           wmma::row_major> bf[2];
#pragma unroll
            for (int r = 0; r < 4; r++) {
                wmma::load_matrix_sync(af[r],
                    &As[p][(wr * 64 + r * 16) * ASTRIDE + kk], ASTRIDE);
#pragma unroll
                for (int t = 0; t < af[r].num_elements; t++)
                    af[r].x[t] = wmma::__float_to_tf32(af[r].x[t]);
            }
#pragma unroll
            for (int c = 0; c < 2; c++) {
                wmma::load_matrix_sync(bf[c],
                    &Bs[p][kk * BSTRIDE + wc * 32 + c * 16], BSTRIDE);
#pragma unroll
                for (int t = 0; t < bf[c].num_elements; t++)
                    bf[c].x[t] = wmma::__float_to_tf32(bf[c].x[t]);
            }
#pragma unroll
            for (int r = 0; r < 4; r++)
#pragma unroll
                for (int c = 0; c < 2; c++)
                    wmma::mma_sync(cf[r][c], af[r], bf[c], cf[r][c]);
        }
        p ^= 1;
    }
    __syncthreads();

    float* Cs = sm;                      // [128][CSTRIDE]
#pragma unroll
    for (int r = 0; r < 4; r++)
#pragma unroll
        for (int c = 0; c < 2; c++)
            wmma::store_matrix_sync(
                &Cs[(wr * 64 + r * 16) * CSTRIDE + wc * 32 + c * 16],
                cf[r][c], CSTRIDE, wmma::mem_row_major);
    __syncthreads();

    const int tx = tid & 15, ty = tid >> 4;
    float bi[8];
    *(float4*)&bi[0] = *(const float4*)(B + tx * 8);
    *(float4*)&bi[4] = *(const float4*)(B + tx * 8 + 4);
#pragma unroll
    for (int i = 0; i < 8; i++) {
        int rl = ty * 8 + i;
        int row = blockRow + rl;
        if (row >= NN) continue;
        float ov[8];
        *(float4*)&ov[0] = *(float4*)&Cs[rl * CSTRIDE + tx * 8];
        *(float4*)&ov[4] = *(float4*)&Cs[rl * CSTRIDE + tx * 8 + 4];
#pragma unroll
        for (int j = 0; j < 8; j++) ov[j] += bi[j];
        float* hp  = d_h  + (size_t)row * HID + tx * 8;
        float* h0p = d_h0 + (size_t)row * HID + tx * 8;
        *(float4*)(hp)      = *(float4*)&ov[0];
        *(float4*)(hp + 4)  = *(float4*)&ov[4];
        *(float4*)(h0p)     = *(float4*)&ov[0];
        *(float4*)(h0p + 4) = *(float4*)&ov[4];
        *(uint4*)(d_h16 + (size_t)row * HID + tx * 8) = pack_half8(ov);
    }
}

// ---------------- aggregation: s = 0.9*(norm-adj @ h) + 0.1*h0 ----------------
// one warp per node; neighbor rows gathered from fp16 mirror (256 B/row),
// fp32 accumulation; self row + h0 stay fp32. 8-way edge unroll.
__global__ __launch_bounds__(256) void k_agg() {
    int i = blockIdx.x * 8 + (threadIdx.x >> 5);
    if (i >= NN) return;
    int lane = threadIdx.x & 31;
    const uint2* h16 = (const uint2*)d_h16;   // 32 x 8B chunks per row
    float di = d_dinv[i];
    float wself = di * di;
    float4 hi = ((const float4*)d_h)[(size_t)i * 32 + lane];
    float4 A0 = make_float4(wself * hi.x, wself * hi.y, wself * hi.z, wself * hi.w);
    float4 A1 = make_float4(0.f, 0.f, 0.f, 0.f);
    float4 A2 = make_float4(0.f, 0.f, 0.f, 0.f);
    float4 A3 = make_float4(0.f, 0.f, 0.f, 0.f);

#define GATHER4(ACC, P)                                                     \
    do {                                                                    \
        uint2 raw = __ldg(&h16[(size_t)(P).x * 32 + lane]);                 \
        float wgt = __int_as_float((P).y);                                  \
        float2 lo = __half22float2(*(__half2*)&raw.x);                      \
        float2 hi2 = __half22float2(*(__half2*)&raw.y);                     \
        ACC.x += wgt * lo.x;  ACC.y += wgt * lo.y;                          \
        ACC.z += wgt * hi2.x; ACC.w += wgt * hi2.y;                         \
    } while (0)

    int beg = d_rowptr[i], end = d_rowptr[i + 1];
    int n = end - beg;
    int e = beg;
    int end8 = beg + (n & ~7);
    for (; e < end8; e += 8) {
        int2 p0 = d_epack[e];
        int2 p1 = d_epack[e + 1];
        int2 p2 = d_epack[e + 2];
        int2 p3 = d_epack[e + 3];
        int2 p4 = d_epack[e + 4];
        int2 p5 = d_epack[e + 5];
        int2 p6 = d_epack[e + 6];
        int2 p7 = d_epack[e + 7];
        GATHER4(A0, p0); GATHER4(A1, p1); GATHER4(A2, p2); GATHER4(A3, p3);
        GATHER4(A0, p4); GATHER4(A1, p5); GATHER4(A2, p6); GATHER4(A3, p7);
    }
    for (; e < end; e++) {
        int2 p0 = d_epack[e];
        GATHER4(A1, p0);
    }
#undef GATHER4

    float4 h0v = ((const float4*)d_h0)[(size_t)i * 32 + lane];
    float4 o;
    o.x = 0.9f * ((A0.x + A1.x) + (A2.x + A3.x)) + 0.1f * h0v.x;
    o.y = 0.9f * ((A0.y + A1.y) + (A2.y + A3.y)) + 0.1f * h0v.y;
    o.z = 0.9f * ((A0.z + A1.z) + (A2.z + A3.z)) + 0.1f * h0v.z;
    o.w = 0.9f * ((A0.w + A1.w) + (A2.w + A3.w)) + 0.1f * h0v.w;
    ((float4*)d_s)[(size_t)i * 32 + lane] = o;
}

// ---------------- layer GEMM (tf32 WMMA) + identity-map mix + ELU ----------
// h = elu((1-beta)*s + beta*(s @ W)); writes fp32 h + fp16 mirror
__global__ __launch_bounds__(256, 2) void k_gemm_layer(const float* __restrict__ W,
                                                       float beta) {
    extern __shared__ float sm[];
    float* As = sm;                      // [128][ASTRIDE]
    float* Bs = sm + 128 * ASTRIDE;      // [32][BSTRIDE]
    const int tid = threadIdx.x;
    const int blockRow = blockIdx.x * 128;
    const int warp = tid >> 5;
    const int wr = warp >> 2;
    const int wc = warp & 3;

    wmma::fragment<wmma::accumulator, 16, 16, 8, float> cf[4][2];
#pragma unroll
    for (int r = 0; r < 4; r++)
#pragma unroll
        for (int c = 0; c < 2; c++)
            wmma::fill_fragment(cf[r][c], 0.f);

    for (int k0 = 0; k0 < HID; k0 += 32) {
#pragma unroll
        for (int j = 0; j < 4; j++) {
            int idx = tid + j * 256;
            int r = idx >> 3, c4 = idx & 7;
            int grow = blockRow + r;
            float4 v = make_float4(0.f, 0.f, 0.f, 0.f);
            if (grow < NN)
                v = *(const float4*)(d_s + (size_t)grow * HID + k0 + c4 * 4);
            *(float4*)&As[r * ASTRIDE + c4 * 4] = v;
        }
#pragma unroll
        for (int j = 0; j < 4; j++) {
            int idx = tid + j * 256;
            int r = idx >> 5, c4 = idx & 31;
            *(float4*)&Bs[r * BSTRIDE + c4 * 4] =
                *(const float4*)(W + (size_t)(k0 + r) * HID + c4 * 4);
        }
        __syncthreads();
#pragma unroll
        for (int kk = 0; kk < 32; kk += 8) {
            wmma::fragment<wmma::matrix_a, 16, 16, 8, wmma::precision::tf32,
                           wmma::row_major> af[4];
            wmma::fragment<wmma::matrix_b, 16, 16, 8, wmma::precision::tf32,
                           wmma::row_major> bf[2];
#pragma unroll
            for (int r = 0; r < 4; r++) {
                wmma::load_matrix_sync(af[r],
                    &As[(wr * 64 + r * 16) * ASTRIDE + kk], ASTRIDE);
#pragma unroll
                for (int t = 0; t < af[r].num_elements; t++)
                    af[r].x[t] = wmma::__float_to_tf32(af[r].x[t]);
            }
#pragma unroll
            for (int c = 0; c < 2; c++) {
                wmma::load_matrix_sync(bf[c],
                    &Bs[kk * BSTRIDE + wc * 32 + c * 16], BSTRIDE);
#pragma unroll
                for (int t = 0; t < bf[c].num_elements; t++)
                    bf[c].x[t] = wmma::__float_to_tf32(bf[c].x[t]);
            }
#pragma unroll
            for (int r = 0; r < 4; r++)
#pragma unroll
                for (int c = 0; c < 2; c++)
                    wmma::mma_sync(cf[r][c], af[r], bf[c], cf[r][c]);
        }
        __syncthreads();
    }

    float* Cs = sm;                      // [128][CSTRIDE]
#pragma unroll
    for (int r = 0; r < 4; r++)
#pragma unroll
        for (int c = 0; c < 2; c++)
            wmma::store_matrix_sync(
                &Cs[(wr * 64 + r * 16) * CSTRIDE + wc * 32 + c * 16],
                cf[r][c], CSTRIDE, wmma::mem_row_major);
    __syncthreads();

    const int tx = tid & 15, ty = tid >> 4;
    const float omb = 1.f - beta;
#pragma unroll
    for (int i = 0; i < 8; i++) {
        int rl = ty * 8 + i;
        int row = blockRow + rl;
        if (row >= NN) continue;
        const float* sp = d_s + (size_t)row * HID + tx * 8;
        float4 s0 = *(const float4*)(sp);
        float4 s1 = *(const float4*)(sp + 4);
        float sv[8] = {s0.x, s0.y, s0.z, s0.w, s1.x, s1.y, s1.z, s1.w};
        float av[8];
        *(float4*)&av[0] = *(float4*)&Cs[rl * CSTRIDE + tx * 8];
        *(float4*)&av[4] = *(float4*)&Cs[rl * CSTRIDE + tx * 8 + 4];
        float ov[8];
#pragma unroll
        for (int j = 0; j < 8; j++) {
            float v = omb * sv[j] + beta * av[j];
            ov[j] = (v > 0.f) ? v : expm1f(v);
        }
        float* hp = d_h + (size_t)row * HID + tx * 8;
        *(float4*)(hp)     = *(float4*)&ov[0];
        *(float4*)(hp + 4) = *(float4*)&ov[4];
        *(uint4*)(d_h16 + (size_t)row * HID + tx * 8) = pack_half8(ov);
    }
}

// ---------------- output GEMM + log_softmax (+ counter re-zero) -------------
__global__ __launch_bounds__(256) void k_out(const float* __restrict__ Wo,
                                             const float* __restrict__ Bo,
                                             float* __restrict__ out) {
    int gid = blockIdx.x * blockDim.x + threadIdx.x;
    if (gid < NN) { d_cnt[gid] = 0; d_fill[gid] = 0; }

    __shared__ float ws[128][64];   // 32 KB
    __shared__ float hs[32][128];   // 16 KB
    const int tid = threadIdx.x;
    const int base = blockIdx.x * 32;
#pragma unroll
    for (int j = 0; j < 8; j++) {
        int idx = tid + j * 256;
        int r = idx >> 4, c4 = idx & 15;
        *(float4*)&ws[r][c4 * 4] = *(const float4*)(Wo + (size_t)r * NC + c4 * 4);
    }
#pragma unroll
    for (int j = 0; j < 4; j++) {
        int idx = tid + j * 256;
        int r = idx >> 5, c4 = idx & 31;
        *(float4*)&hs[r][c4 * 4] =
            *(const float4*)(d_h + (size_t)(base + r) * HID + c4 * 4);
    }
    __syncthreads();
    const int w = tid >> 5, lane = tid & 31;
    float b0 = Bo[lane], b1 = Bo[lane + 32];
    float acc[4][2];
#pragma unroll
    for (int r = 0; r < 4; r++) { acc[r][0] = 0.f; acc[r][1] = 0.f; }
    for (int k = 0; k < HID; k++) {
        float wv0 = ws[k][lane];
        float wv1 = ws[k][lane + 32];
#pragma unroll
        for (int r = 0; r < 4; r++) {
            float hv = hs[w * 4 + r][k];
            acc[r][0] += hv * wv0;
            acc[r][1] += hv * wv1;
        }
    }
#pragma unroll
    for (int r = 0; r < 4; r++) {
        int row = base + w * 4 + r;
        float v0 = acc[r][0] + b0;
        float v1 = acc[r][1] + b1;
        float m = fmaxf(v0, v1);
#pragma unroll
        for (int off = 16; off; off >>= 1)
            m = fmaxf(m, __shfl_xor_sync(0xffffffff, m, off));
        float ssum = expf(v0 - m) + expf(v1 - m);
#pragma unroll
        for (int off = 16; off; off >>= 1)
            ssum += __shfl_xor_sync(0xffffffff, ssum, off);
        float lse = m + logf(ssum);
        out[(size_t)row * NC + lane]      = v0 - lse;
        out[(size_t)row * NC + lane + 32] = v1 - lse;
    }
}

// ---------------- launch ----------------
extern "C" void kernel_launch(void* const* d_in, const int* in_sizes, int n_in,
                              void* d_out, int out_size) {
    const float* x      = (const float*)d_in[0];
    const void*  ei     = d_in[1];
    const float* w_in   = (const float*)d_in[2];
    const float* b_in   = (const float*)d_in[3];
    const float* conv_w = (const float*)d_in[4];
    const float* w_out  = (const float*)d_in[5];
    const float* b_out  = (const float*)d_in[6];
    float*       out    = (float*)d_out;

    cudaFuncSetAttribute(k_gemm_in_scatter,
                         cudaFuncAttributeMaxDynamicSharedMemorySize, INGEMM_SMEM);
    cudaFuncSetAttribute(k_gemm_layer,
                         cudaFuncAttributeMaxDynamicSharedMemorySize, LGEMM_SMEM);

    k_prep_edges<<<SC_BLOCKS, 256>>>(ei);                               // 0
    k_scan_dinv<<<1, 1024>>>();                                         // 1
    k_gemm_in_scatter<<<GEMM_BLOCKS + SC_BLOCKS, 256, INGEMM_SMEM>>>(
        x, w_in, b_in);                                                 // 2

    for (int l = 0; l < NL; l++) {                                      // 3..18
        float beta = (float)log(0.5 / (double)(l + 1) + 1.0);
        k_agg<<<(NN + 7) / 8, 256>>>();           // slot 3 = profiled
        k_gemm_layer<<<GEMM_BLOCKS, 256, LGEMM_SMEM>>>(
            conv_w + (size_t)l * HID * HID, beta);
    }

    k_out<<<NN / 32, 256>>>(w_out, b_out, out);
}

// round 13
// speedup vs baseline: 1.4207x; 1.1023x over previous
#include <cuda_runtime.h>
#include <cuda_fp16.h>
#include <math.h>
#include <stdint.h>
#include <mma.h>

using namespace nvcuda;

// Problem constants (GCNII_30794915512599)
#define NN   100000      // nodes
#define NE   1600000     // edges
#define FIN  512
#define HID  128
#define NC   64
#define NL   8

#define GEMM_BLOCKS ((NN + 127) / 128)          // 782
#define SC_BLOCKS   ((NE + 255) / 256)          // 6250

// wmma GEMM smem geometry
#define ASTRIDE 36                               // 32 + 4 pad
#define BSTRIDE 132                              // 128 + 4 pad
#define CSTRIDE 132
#define LGEMM_SMEM (128 * CSTRIDE * 4)           // 67584 B

// tf32 input-GEMM smem: As[2][128][36] + Bs[2][32][132]; C overlays
#define IN_AS_STAGE (128 * ASTRIDE)
#define IN_BS_STAGE (32 * BSTRIDE)
#define IN_SMEM_FLOATS (2 * IN_AS_STAGE + 2 * IN_BS_STAGE)   // 17664
#define INGEMM_SMEM (IN_SMEM_FLOATS * 4)         // 70656 B

// ---------------- scratch (static __device__ — no allocations) ----------------
__device__ int    d_cnt[NN];     // zero-init at load; re-zeroed by k_out each launch
__device__ int    d_fill[NN];
__device__ int    d_rowptr[NN + 1];
__device__ float  d_dinv[NN];
__device__ int    d_src[NE];
__device__ int    d_dst[NE];
__device__ int2   d_epack[NE];   // packed (src, weight-as-int)
__device__ __half d_h16 [(size_t)NN * HID];  // h  (fp16 only)
__device__ __half d_h016[(size_t)NN * HID];  // h0 (fp16 only)
__device__ __half d_s16 [(size_t)NN * HID];  // s  (fp16 only)

// ---------------- cp.async helpers ----------------
__device__ __forceinline__ void cp_async16(uint32_t saddr, const void* gptr) {
    asm volatile("cp.async.ca.shared.global [%0], [%1], 16;"
                 :: "r"(saddr), "l"(gptr));
}
__device__ __forceinline__ void cp_commit() {
    asm volatile("cp.async.commit_group;");
}
__device__ __forceinline__ void cp_wait0() {
    asm volatile("cp.async.wait_group 0;");
}
__device__ __forceinline__ uint32_t smem_u32(const void* p) {
    return (uint32_t)__cvta_generic_to_shared(p);
}

// pack 8 floats -> 8 halfs (16B)
__device__ __forceinline__ uint4 pack_half8(const float* v) {
    __half2 q0 = __floats2half2_rn(v[0], v[1]);
    __half2 q1 = __floats2half2_rn(v[2], v[3]);
    __half2 q2 = __floats2half2_rn(v[4], v[5]);
    __half2 q3 = __floats2half2_rn(v[6], v[7]);
    uint4 u;
    u.x = *(uint32_t*)&q0; u.y = *(uint32_t*)&q1;
    u.z = *(uint32_t*)&q2; u.w = *(uint32_t*)&q3;
    return u;
}
// unpack 8 halfs (uint4) -> 8 floats
__device__ __forceinline__ void unpack_half8(uint4 u, float* v) {
    float2 a = __half22float2(*(__half2*)&u.x);
    float2 b = __half22float2(*(__half2*)&u.y);
    float2 c = __half22float2(*(__half2*)&u.z);
    float2 d = __half22float2(*(__half2*)&u.w);
    v[0] = a.x; v[1] = a.y; v[2] = b.x; v[3] = b.y;
    v[4] = c.x; v[5] = c.y; v[6] = d.x; v[7] = d.y;
}

// ---------------- edge prep (with inline per-warp dtype detection) ----------
// edge_index is logically int64 but JAX without x64 emits int32. int32 pairs
// read as uint64 are >= 2^32 whenever the high word is nonzero; true int64
// indices are < 100000.
__global__ __launch_bounds__(256) void k_prep_edges(const void* eiv) {
    const int lane = threadIdx.x & 31;
    const unsigned long long* q = (const unsigned long long*)eiv;
    bool big = false;
#pragma unroll
    for (int k = 0; k < 2; k++) {
        int idx = (lane + k * 32) * 31;      // samples in [0, 1953]
        big |= (q[idx] > 0xFFFFFFFFull);
    }
    bool is64 = !__any_sync(0xffffffff, big);

    int e = blockIdx.x * blockDim.x + threadIdx.x;
    if (e >= NE) return;
    int s, d;
    if (is64) {
        const long long* ei = (const long long*)eiv;
        s = (int)ei[e];
        d = (int)ei[(size_t)NE + e];
    } else {
        const int* ei = (const int*)eiv;
        s = ei[e];
        d = ei[NE + e];
    }
    s = min(max(s, 0), NN - 1);
    d = min(max(d, 0), NN - 1);
    d_src[e] = s;
    d_dst[e] = d;
    atomicAdd(&d_cnt[d], 1);
}

// single-block exclusive scan over d_cnt -> d_rowptr, fused with dinv compute
__global__ __launch_bounds__(1024) void k_scan_dinv() {
    __shared__ int buf[1024];
    const int t = threadIdx.x;
    const int CH = (NN + 1023) / 1024;   // 98
    const int start = t * CH;
    int s = 0;
    for (int j = 0; j < CH; j++) {
        int idx = start + j;
        if (idx < NN) s += d_cnt[idx];
    }
    buf[t] = s;
    __syncthreads();
    for (int off = 1; off < 1024; off <<= 1) {
        int v = (t >= off) ? buf[t - off] : 0;
        __syncthreads();
        buf[t] += v;
        __syncthreads();
    }
    int run = (t == 0) ? 0 : buf[t - 1];
    for (int j = 0; j < CH; j++) {
        int idx = start + j;
        if (idx < NN) {
            int c = d_cnt[idx];
            d_rowptr[idx] = run;
            d_dinv[idx] = rsqrtf((float)(c + 1));   // +1 self loop
            run += c;
        }
    }
    if (t == 1023) d_rowptr[NN] = buf[1023];
}

// ---------------- fused: tf32 input GEMM (blocks [0,782)) + scatter (rest) --
// gemm: h = x @ w_in + b_in ; writes h16 and h016 (fp16 only)
__global__ __launch_bounds__(256, 2) void k_gemm_in_scatter(
        const float* __restrict__ X, const float* __restrict__ W,
        const float* __restrict__ B) {
    if (blockIdx.x >= GEMM_BLOCKS) {
        int e = (blockIdx.x - GEMM_BLOCKS) * 256 + threadIdx.x;
        if (e < NE) {
            int s = d_src[e], d = d_dst[e];
            int pos = d_rowptr[d] + atomicAdd(&d_fill[d], 1);
            float w = d_dinv[s] * d_dinv[d];
            d_epack[pos] = make_int2(s, __float_as_int(w));
        }
        return;
    }
    extern __shared__ float sm[];
    float* As[2] = { sm, sm + IN_AS_STAGE };
    float* Bs[2] = { sm + 2 * IN_AS_STAGE, sm + 2 * IN_AS_STAGE + IN_BS_STAGE };
    const int tid = threadIdx.x;
    const int blockRow = blockIdx.x * 128;
    const int warp = tid >> 5;
    const int wr = warp >> 2;            // 0..1
    const int wc = warp & 3;             // 0..3

    const int ar = tid >> 1, ac = tid & 1;
    const int brr = tid >> 3, bcc = tid & 7;

    wmma::fragment<wmma::accumulator, 16, 16, 8, float> cf[4][2];
#pragma unroll
    for (int r = 0; r < 4; r++)
#pragma unroll
        for (int c = 0; c < 2; c++)
            wmma::fill_fragment(cf[r][c], 0.f);

    const int asrc0 = min(blockRow + ar, NN - 1);

    auto issue_stage = [&](int buf, int k0) {
#pragma unroll
        for (int j = 0; j < 4; j++) {
            int c = ac + j * 2;
            cp_async16(smem_u32(&As[buf][ar * ASTRIDE + c * 4]),
                       X + (size_t)asrc0 * FIN + k0 + c * 4);
        }
#pragma unroll
        for (int j = 0; j < 4; j++) {
            int c = bcc + j * 8;
            cp_async16(smem_u32(&Bs[buf][brr * BSTRIDE + c * 4]),
                       W + (size_t)(k0 + brr) * HID + c * 4);
        }
        cp_commit();
    };

    issue_stage(0, 0);
    int p = 0;
    for (int s = 0; s < FIN / 32; s++) {
        cp_wait0();
        __syncthreads();
        if (s + 1 < FIN / 32) issue_stage(p ^ 1, (s + 1) * 32);
#pragma unroll
        for (int kk = 0; kk < 32; kk += 8) {
            wmma::fragment<wmma::matrix_a, 16, 16, 8, wmma::precision::tf32,
                           wmma::row_major> af[4];
            wmma::fragment<wmma::matrix_b, 16, 16, 8, wmma::precision::tf32,
                           wmma::row_major> bf[2];
#pragma unroll
            for (int r = 0; r < 4; r++) {
                wmma::load_matrix_sync(af[r],
                    &As[p][(wr * 64 + r * 16) * ASTRIDE + kk], ASTRIDE);
#pragma unroll
                for (int t = 0; t < af[r].num_elements; t++)
                    af[r].x[t] = wmma::__float_to_tf32(af[r].x[t]);
            }
#pragma unroll
            for (int c = 0; c < 2; c++) {
                wmma::load_matrix_sync(bf[c],
                    &Bs[p][kk * BSTRIDE + wc * 32 + c * 16], BSTRIDE);
#pragma unroll
                for (int t = 0; t < bf[c].num_elements; t++)
                    bf[c].x[t] = wmma::__float_to_tf32(bf[c].x[t]);
            }
#pragma unroll
            for (int r = 0; r < 4; r++)
#pragma unroll
                for (int c = 0; c < 2; c++)
                    wmma::mma_sync(cf[r][c], af[r], bf[c], cf[r][c]);
        }
        p ^= 1;
    }
    __syncthreads();

    float* Cs = sm;                      // [128][CSTRIDE]
#pragma unroll
    for (int r = 0; r < 4; r++)
#pragma unroll
        for (int c = 0; c < 2; c++)
            wmma::store_matrix_sync(
                &Cs[(wr * 64 + r * 16) * CSTRIDE + wc * 32 + c * 16],
                cf[r][c], CSTRIDE, wmma::mem_row_major);
    __syncthreads();

    const int tx = tid & 15, ty = tid >> 4;
    float bi[8];
    *(float4*)&bi[0] = *(const float4*)(B + tx * 8);
    *(float4*)&bi[4] = *(const float4*)(B + tx * 8 + 4);
#pragma unroll
    for (int i = 0; i < 8; i++) {
        int rl = ty * 8 + i;
        int row = blockRow + rl;
        if (row >= NN) continue;
        float ov[8];
        *(float4*)&ov[0] = *(float4*)&Cs[rl * CSTRIDE + tx * 8];
        *(float4*)&ov[4] = *(float4*)&Cs[rl * CSTRIDE + tx * 8 + 4];
#pragma unroll
        for (int j = 0; j < 8; j++) ov[j] += bi[j];
        uint4 hv = pack_half8(ov);
        *(uint4*)(d_h16  + (size_t)row * HID + tx * 8) = hv;
        *(uint4*)(d_h016 + (size_t)row * HID + tx * 8) = hv;
    }
}

// ---------------- aggregation: s = 0.9*(norm-adj @ h) + 0.1*h0 ----------------
// one warp per node; all arrays fp16, fp32 accumulation; 8-way edge unroll
__global__ __launch_bounds__(256) void k_agg() {
    int i = blockIdx.x * 8 + (threadIdx.x >> 5);
    if (i >= NN) return;
    int lane = threadIdx.x & 31;
    const uint2* h16 = (const uint2*)d_h16;   // 32 x 8B chunks per row
    float di = d_dinv[i];
    float wself = di * di;
    float4 A0, A1, A2, A3;
    {
        uint2 raw = h16[(size_t)i * 32 + lane];
        float2 lo = __half22float2(*(__half2*)&raw.x);
        float2 hi2 = __half22float2(*(__half2*)&raw.y);
        A0 = make_float4(wself * lo.x, wself * lo.y, wself * hi2.x, wself * hi2.y);
    }
    A1 = make_float4(0.f, 0.f, 0.f, 0.f);
    A2 = make_float4(0.f, 0.f, 0.f, 0.f);
    A3 = make_float4(0.f, 0.f, 0.f, 0.f);

#define GATHER4(ACC, P)                                                     \
    do {                                                                    \
        uint2 raw = __ldg(&h16[(size_t)(P).x * 32 + lane]);                 \
        float wgt = __int_as_float((P).y);                                  \
        float2 lo = __half22float2(*(__half2*)&raw.x);                      \
        float2 hi2 = __half22float2(*(__half2*)&raw.y);                     \
        ACC.x += wgt * lo.x;  ACC.y += wgt * lo.y;                          \
        ACC.z += wgt * hi2.x; ACC.w += wgt * hi2.y;                         \
    } while (0)

    int beg = d_rowptr[i], end = d_rowptr[i + 1];
    int n = end - beg;
    int e = beg;
    int end8 = beg + (n & ~7);
    for (; e < end8; e += 8) {
        int2 p0 = d_epack[e];
        int2 p1 = d_epack[e + 1];
        int2 p2 = d_epack[e + 2];
        int2 p3 = d_epack[e + 3];
        int2 p4 = d_epack[e + 4];
        int2 p5 = d_epack[e + 5];
        int2 p6 = d_epack[e + 6];
        int2 p7 = d_epack[e + 7];
        GATHER4(A0, p0); GATHER4(A1, p1); GATHER4(A2, p2); GATHER4(A3, p3);
        GATHER4(A0, p4); GATHER4(A1, p5); GATHER4(A2, p6); GATHER4(A3, p7);
    }
    for (; e < end; e++) {
        int2 p0 = d_epack[e];
        GATHER4(A1, p0);
    }
#undef GATHER4

    uint2 h0raw = ((const uint2*)d_h016)[(size_t)i * 32 + lane];
    float2 h0lo = __half22float2(*(__half2*)&h0raw.x);
    float2 h0hi = __half22float2(*(__half2*)&h0raw.y);
    float o[4];
    o[0] = 0.9f * ((A0.x + A1.x) + (A2.x + A3.x)) + 0.1f * h0lo.x;
    o[1] = 0.9f * ((A0.y + A1.y) + (A2.y + A3.y)) + 0.1f * h0lo.y;
    o[2] = 0.9f * ((A0.z + A1.z) + (A2.z + A3.z)) + 0.1f * h0hi.x;
    o[3] = 0.9f * ((A0.w + A1.w) + (A2.w + A3.w)) + 0.1f * h0hi.y;
    __half2 q0 = __floats2half2_rn(o[0], o[1]);
    __half2 q1 = __floats2half2_rn(o[2], o[3]);
    uint2 u;
    u.x = *(uint32_t*)&q0; u.y = *(uint32_t*)&q1;
    ((uint2*)d_s16)[(size_t)i * 32 + lane] = u;
}

// ---------------- layer GEMM (tf32 WMMA) + identity-map mix + ELU ----------
// h = elu((1-beta)*s + beta*(s @ W)); s read fp16, h written fp16
__global__ __launch_bounds__(256, 2) void k_gemm_layer(const float* __restrict__ W,
                                                       float beta) {
    extern __shared__ float sm[];
    float* As = sm;                      // [128][ASTRIDE]
    float* Bs = sm + 128 * ASTRIDE;      // [32][BSTRIDE]
    const int tid = threadIdx.x;
    const int blockRow = blockIdx.x * 128;
    const int warp = tid >> 5;
    const int wr = warp >> 2;
    const int wc = warp & 3;

    wmma::fragment<wmma::accumulator, 16, 16, 8, float> cf[4][2];
#pragma unroll
    for (int r = 0; r < 4; r++)
#pragma unroll
        for (int c = 0; c < 2; c++)
            wmma::fill_fragment(cf[r][c], 0.f);

    for (int k0 = 0; k0 < HID; k0 += 32) {
        // A tile: s16[blockRow..+128][k0..+32] -> fp32 smem
#pragma unroll
        for (int j = 0; j < 2; j++) {
            int idx = tid + j * 256;          // 512 chunks of 8 halfs
            int r = idx >> 2, c8 = idx & 3;
            int grow = blockRow + r;
            float v[8] = {0.f};
            if (grow < NN) {
                uint4 raw = *(const uint4*)(d_s16 + (size_t)grow * HID + k0 + c8 * 8);
                unpack_half8(raw, v);
            }
            *(float4*)&As[r * ASTRIDE + c8 * 8]     = *(float4*)&v[0];
            *(float4*)&As[r * ASTRIDE + c8 * 8 + 4] = *(float4*)&v[4];
        }
#pragma unroll
        for (int j = 0; j < 4; j++) {
            int idx = tid + j * 256;
            int r = idx >> 5, c4 = idx & 31;
            *(float4*)&Bs[r * BSTRIDE + c4 * 4] =
                *(const float4*)(W + (size_t)(k0 + r) * HID + c4 * 4);
        }
        __syncthreads();
#pragma unroll
        for (int kk = 0; kk < 32; kk += 8) {
            wmma::fragment<wmma::matrix_a, 16, 16, 8, wmma::precision::tf32,
                           wmma::row_major> af[4];
            wmma::fragment<wmma::matrix_b, 16, 16, 8, wmma::precision::tf32,
                           wmma::row_major> bf[2];
#pragma unroll
            for (int r = 0; r < 4; r++) {
                wmma::load_matrix_sync(af[r],
                    &As[(wr * 64 + r * 16) * ASTRIDE + kk], ASTRIDE);
#pragma unroll
                for (int t = 0; t < af[r].num_elements; t++)
                    af[r].x[t] = wmma::__float_to_tf32(af[r].x[t]);
            }
#pragma unroll
            for (int c = 0; c < 2; c++) {
                wmma::load_matrix_sync(bf[c],
                    &Bs[kk * BSTRIDE + wc * 32 + c * 16], BSTRIDE);
#pragma unroll
                for (int t = 0; t < bf[c].num_elements; t++)
                    bf[c].x[t] = wmma::__float_to_tf32(bf[c].x[t]);
            }
#pragma unroll
            for (int r = 0; r < 4; r++)
#pragma unroll
                for (int c = 0; c < 2; c++)
                    wmma::mma_sync(cf[r][c], af[r], bf[c], cf[r][c]);
        }
        __syncthreads();
    }

    float* Cs = sm;                      // [128][CSTRIDE]
#pragma unroll
    for (int r = 0; r < 4; r++)
#pragma unroll
        for (int c = 0; c < 2; c++)
            wmma::store_matrix_sync(
                &Cs[(wr * 64 + r * 16) * CSTRIDE + wc * 32 + c * 16],
                cf[r][c], CSTRIDE, wmma::mem_row_major);
    __syncthreads();

    const int tx = tid & 15, ty = tid >> 4;
    const float omb = 1.f - beta;
#pragma unroll
    for (int i = 0; i < 8; i++) {
        int rl = ty * 8 + i;
        int row = blockRow + rl;
        if (row >= NN) continue;
        float sv[8];
        uint4 sraw = *(const uint4*)(d_s16 + (size_t)row * HID + tx * 8);
        unpack_half8(sraw, sv);
        float av[8];
        *(float4*)&av[0] = *(float4*)&Cs[rl * CSTRIDE + tx * 8];
        *(float4*)&av[4] = *(float4*)&Cs[rl * CSTRIDE + tx * 8 + 4];
        float ov[8];
#pragma unroll
        for (int j = 0; j < 8; j++) {
            float v = omb * sv[j] + beta * av[j];
            ov[j] = (v > 0.f) ? v : expm1f(v);
        }
        *(uint4*)(d_h16 + (size_t)row * HID + tx * 8) = pack_half8(ov);
    }
}

// ---------------- output GEMM + log_softmax (+ counter re-zero) -------------
__global__ __launch_bounds__(256) void k_out(const float* __restrict__ Wo,
                                             const float* __restrict__ Bo,
                                             float* __restrict__ out) {
    int gid = blockIdx.x * blockDim.x + threadIdx.x;
    if (gid < NN) { d_cnt[gid] = 0; d_fill[gid] = 0; }

    __shared__ float ws[128][64];   // 32 KB
    __shared__ float hs[32][128];   // 16 KB
    const int tid = threadIdx.x;
    const int base = blockIdx.x * 32;
#pragma unroll
    for (int j = 0; j < 8; j++) {
        int idx = tid + j * 256;
        int r = idx >> 4, c4 = idx & 15;
        *(float4*)&ws[r][c4 * 4] = *(const float4*)(Wo + (size_t)r * NC + c4 * 4);
    }
    // h rows from fp16: 32 rows x 128 halfs = 512 chunks of 8
#pragma unroll
    for (int j = 0; j < 2; j++) {
        int idx = tid + j * 256;
        int r = idx >> 4, c8 = idx & 15;
        uint4 raw = *(const uint4*)(d_h16 + (size_t)(base + r) * HID + c8 * 8);
        float v[8];
        unpack_half8(raw, v);
        *(float4*)&hs[r][c8 * 8]     = *(float4*)&v[0];
        *(float4*)&hs[r][c8 * 8 + 4] = *(float4*)&v[4];
    }
    __syncthreads();
    const int w = tid >> 5, lane = tid & 31;
    float b0 = Bo[lane], b1 = Bo[lane + 32];
    float acc[4][2];
#pragma unroll
    for (int r = 0; r < 4; r++) { acc[r][0] = 0.f; acc[r][1] = 0.f; }
    for (int k = 0; k < HID; k++) {
        float wv0 = ws[k][lane];
        float wv1 = ws[k][lane + 32];
#pragma unroll
        for (int r = 0; r < 4; r++) {
            float hv = hs[w * 4 + r][k];
            acc[r][0] += hv * wv0;
            acc[r][1] += hv * wv1;
        }
    }
#pragma unroll
    for (int r = 0; r < 4; r++) {
        int row = base + w * 4 + r;
        float v0 = acc[r][0] + b0;
        float v1 = acc[r][1] + b1;
        float m = fmaxf(v0, v1);
#pragma unroll
        for (int off = 16; off; off >>= 1)
            m = fmaxf(m, __shfl_xor_sync(0xffffffff, m, off));
        float ssum = expf(v0 - m) + expf(v1 - m);
#pragma unroll
        for (int off = 16; off; off >>= 1)
            ssum += __shfl_xor_sync(0xffffffff, ssum, off);
        float lse = m + logf(ssum);
        out[(size_t)row * NC + lane]      = v0 - lse;
        out[(size_t)row * NC + lane + 32] = v1 - lse;
    }
}

// ---------------- launch ----------------
extern "C" void kernel_launch(void* const* d_in, const int* in_sizes, int n_in,
                              void* d_out, int out_size) {
    const float* x      = (const float*)d_in[0];
    const void*  ei     = d_in[1];
    const float* w_in   = (const float*)d_in[2];
    const float* b_in   = (const float*)d_in[3];
    const float* conv_w = (const float*)d_in[4];
    const float* w_out  = (const float*)d_in[5];
    const float* b_out  = (const float*)d_in[6];
    float*       out    = (float*)d_out;

    cudaFuncSetAttribute(k_gemm_in_scatter,
                         cudaFuncAttributeMaxDynamicSharedMemorySize, INGEMM_SMEM);
    cudaFuncSetAttribute(k_gemm_layer,
                         cudaFuncAttributeMaxDynamicSharedMemorySize, LGEMM_SMEM);

    k_prep_edges<<<SC_BLOCKS, 256>>>(ei);                               // 0
    k_scan_dinv<<<1, 1024>>>();                                         // 1
    k_gemm_in_scatter<<<GEMM_BLOCKS + SC_BLOCKS, 256, INGEMM_SMEM>>>(
        x, w_in, b_in);                                                 // 2

    for (int l = 0; l < NL; l++) {                                      // 3..18
        float beta = (float)log(0.5 / (double)(l + 1) + 1.0);
        k_agg<<<(NN + 7) / 8, 256>>>();           // slot 3 = profiled
        k_gemm_layer<<<GEMM_BLOCKS, 256, LGEMM_SMEM>>>(
            conv_w + (size_t)l * HID * HID, beta);
    }

    k_out<<<NN / 32, 256>>>(w_out, b_out, out);
}

// round 14
// speedup vs baseline: 1.8716x; 1.3174x over previous
#include <cuda_runtime.h>
#include <cuda_fp16.h>
#include <math.h>
#include <stdint.h>
#include <mma.h>

using namespace nvcuda;

// Problem constants (GCNII_30794915512599)
#define NN   100000      // nodes
#define NE   1600000     // edges
#define FIN  512
#define HID  128
#define NC   64
#define NL   8

#define GEMM_BLOCKS ((NN + 127) / 128)          // 782
#define SC_BLOCKS   ((NE + 255) / 256)          // 6250

// tf32 input-GEMM smem: As[2][128][36] + Bs[2][32][132]; C overlays
#define ASTRIDE 36
#define BSTRIDE 132
#define CSTRIDE 132
#define IN_AS_STAGE (128 * ASTRIDE)
#define IN_BS_STAGE (32 * BSTRIDE)
#define IN_SMEM_FLOATS (2 * IN_AS_STAGE + 2 * IN_BS_STAGE)   // 17664
#define INGEMM_SMEM (IN_SMEM_FLOATS * 4)         // 70656 B

// fp16 layer-GEMM smem: Ah[128][136] + Bh[128][136] halfs; C fp32 overlays
#define AH_STRIDE 136
#define LGEMM_SMEM (2 * 128 * AH_STRIDE * 2)     // 69632 B (> C overlay 67584)

// ---------------- scratch (static __device__ — no allocations) ----------------
__device__ int    d_cnt[NN];     // zero-init at load; re-zeroed by k_out each launch
__device__ int    d_fill[NN];
__device__ int    d_rowptr[NN + 1];
__device__ float  d_dinv[NN];
__device__ int    d_src[NE];
__device__ int    d_dst[NE];
__device__ int2   d_epack[NE];   // packed (src, weight-as-int)
__device__ __half d_h16 [(size_t)NN * HID];  // h  (fp16 only)
__device__ __half d_h016[(size_t)NN * HID];  // h0 (fp16 only)
__device__ __half d_s16 [(size_t)NN * HID];  // s  (fp16 only)
__device__ __half d_w16 [(size_t)NL * HID * HID];  // fp16 conv weights

// ---------------- cp.async helpers ----------------
__device__ __forceinline__ void cp_async16(uint32_t saddr, const void* gptr) {
    asm volatile("cp.async.ca.shared.global [%0], [%1], 16;"
                 :: "r"(saddr), "l"(gptr));
}
__device__ __forceinline__ void cp_commit() {
    asm volatile("cp.async.commit_group;");
}
__device__ __forceinline__ void cp_wait0() {
    asm volatile("cp.async.wait_group 0;");
}
__device__ __forceinline__ uint32_t smem_u32(const void* p) {
    return (uint32_t)__cvta_generic_to_shared(p);
}

// pack 8 floats -> 8 halfs (16B)
__device__ __forceinline__ uint4 pack_half8(const float* v) {
    __half2 q0 = __floats2half2_rn(v[0], v[1]);
    __half2 q1 = __floats2half2_rn(v[2], v[3]);
    __half2 q2 = __floats2half2_rn(v[4], v[5]);
    __half2 q3 = __floats2half2_rn(v[6], v[7]);
    uint4 u;
    u.x = *(uint32_t*)&q0; u.y = *(uint32_t*)&q1;
    u.z = *(uint32_t*)&q2; u.w = *(uint32_t*)&q3;
    return u;
}
// unpack 8 halfs (uint4) -> 8 floats
__device__ __forceinline__ void unpack_half8(uint4 u, float* v) {
    float2 a = __half22float2(*(__half2*)&u.x);
    float2 b = __half22float2(*(__half2*)&u.y);
    float2 c = __half22float2(*(__half2*)&u.z);
    float2 d = __half22float2(*(__half2*)&u.w);
    v[0] = a.x; v[1] = a.y; v[2] = b.x; v[3] = b.y;
    v[4] = c.x; v[5] = c.y; v[6] = d.x; v[7] = d.y;
}

// ---------------- edge prep (with inline per-warp dtype detection) ----------
// edge_index is logically int64 but JAX without x64 emits int32. int32 pairs
// read as uint64 are >= 2^32 whenever the high word is nonzero; true int64
// indices are < 100000.
__global__ __launch_bounds__(256) void k_prep_edges(const void* eiv) {
    const int lane = threadIdx.x & 31;
    const unsigned long long* q = (const unsigned long long*)eiv;
    bool big = false;
#pragma unroll
    for (int k = 0; k < 2; k++) {
        int idx = (lane + k * 32) * 31;      // samples in [0, 1953]
        big |= (q[idx] > 0xFFFFFFFFull);
    }
    bool is64 = !__any_sync(0xffffffff, big);

    int e = blockIdx.x * blockDim.x + threadIdx.x;
    if (e >= NE) return;
    int s, d;
    if (is64) {
        const long long* ei = (const long long*)eiv;
        s = (int)ei[e];
        d = (int)ei[(size_t)NE + e];
    } else {
        const int* ei = (const int*)eiv;
        s = ei[e];
        d = ei[NE + e];
    }
    s = min(max(s, 0), NN - 1);
    d = min(max(d, 0), NN - 1);
    d_src[e] = s;
    d_dst[e] = d;
    atomicAdd(&d_cnt[d], 1);
}

// single-block exclusive scan over d_cnt -> d_rowptr, fused with dinv compute
__global__ __launch_bounds__(1024) void k_scan_dinv() {
    __shared__ int buf[1024];
    const int t = threadIdx.x;
    const int CH = (NN + 1023) / 1024;   // 98
    const int start = t * CH;
    int s = 0;
    for (int j = 0; j < CH; j++) {
        int idx = start + j;
        if (idx < NN) s += d_cnt[idx];
    }
    buf[t] = s;
    __syncthreads();
    for (int off = 1; off < 1024; off <<= 1) {
        int v = (t >= off) ? buf[t - off] : 0;
        __syncthreads();
        buf[t] += v;
        __syncthreads();
    }
    int run = (t == 0) ? 0 : buf[t - 1];
    for (int j = 0; j < CH; j++) {
        int idx = start + j;
        if (idx < NN) {
            int c = d_cnt[idx];
            d_rowptr[idx] = run;
            d_dinv[idx] = rsqrtf((float)(c + 1));   // +1 self loop
            run += c;
        }
    }
    if (t == 1023) d_rowptr[NN] = buf[1023];
}

// ---------------- conv weight fp32 -> fp16 mirror (once per launch) --------
__global__ __launch_bounds__(256) void k_wconv(const float* __restrict__ CW) {
    int idx = blockIdx.x * 256 + threadIdx.x;    // 32768 threads x 4 floats
    float4 v = *(const float4*)(CW + (size_t)idx * 4);
    __half2 q0 = __floats2half2_rn(v.x, v.y);
    __half2 q1 = __floats2half2_rn(v.z, v.w);
    uint2 u;
    u.x = *(uint32_t*)&q0; u.y = *(uint32_t*)&q1;
    *(uint2*)(d_w16 + (size_t)idx * 4) = u;
}

// ---------------- fused: tf32 input GEMM (blocks [0,782)) + scatter (rest) --
// gemm: h = x @ w_in + b_in ; writes h16 and h016 (fp16 only)
__global__ __launch_bounds__(256, 2) void k_gemm_in_scatter(
        const float* __restrict__ X, const float* __restrict__ W,
        const float* __restrict__ B) {
    if (blockIdx.x >= GEMM_BLOCKS) {
        int e = (blockIdx.x - GEMM_BLOCKS) * 256 + threadIdx.x;
        if (e < NE) {
            int s = d_src[e], d = d_dst[e];
            int pos = d_rowptr[d] + atomicAdd(&d_fill[d], 1);
            float w = d_dinv[s] * d_dinv[d];
            d_epack[pos] = make_int2(s, __float_as_int(w));
        }
        return;
    }
    extern __shared__ float sm[];
    float* As[2] = { sm, sm + IN_AS_STAGE };
    float* Bs[2] = { sm + 2 * IN_AS_STAGE, sm + 2 * IN_AS_STAGE + IN_BS_STAGE };
    const int tid = threadIdx.x;
    const int blockRow = blockIdx.x * 128;
    const int warp = tid >> 5;
    const int wr = warp >> 2;            // 0..1
    const int wc = warp & 3;             // 0..3

    const int ar = tid >> 1, ac = tid & 1;
    const int brr = tid >> 3, bcc = tid & 7;

    wmma::fragment<wmma::accumulator, 16, 16, 8, float> cf[4][2];
#pragma unroll
    for (int r = 0; r < 4; r++)
#pragma unroll
        for (int c = 0; c < 2; c++)
            wmma::fill_fragment(cf[r][c], 0.f);

    const int asrc0 = min(blockRow + ar, NN - 1);

    auto issue_stage = [&](int buf, int k0) {
#pragma unroll
        for (int j = 0; j < 4; j++) {
            int c = ac + j * 2;
            cp_async16(smem_u32(&As[buf][ar * ASTRIDE + c * 4]),
                       X + (size_t)asrc0 * FIN + k0 + c * 4);
        }
#pragma unroll
        for (int j = 0; j < 4; j++) {
            int c = bcc + j * 8;
            cp_async16(smem_u32(&Bs[buf][brr * BSTRIDE + c * 4]),
                       W + (size_t)(k0 + brr) * HID + c * 4);
        }
        cp_commit();
    };

    issue_stage(0, 0);
    int p = 0;
    for (int s = 0; s < FIN / 32; s++) {
        cp_wait0();
        __syncthreads();
        if (s + 1 < FIN / 32) issue_stage(p ^ 1, (s + 1) * 32);
#pragma unroll
        for (int kk = 0; kk < 32; kk += 8) {
            wmma::fragment<wmma::matrix_a, 16, 16, 8, wmma::precision::tf32,
                           wmma::row_major> af[4];
            wmma::fragment<wmma::matrix_b, 16, 16, 8, wmma::precision::tf32,
                           wmma::row_major> bf[2];
#pragma unroll
            for (int r = 0; r < 4; r++) {
                wmma::load_matrix_sync(af[r],
                    &As[p][(wr * 64 + r * 16) * ASTRIDE + kk], ASTRIDE);
#pragma unroll
                for (int t = 0; t < af[r].num_elements; t++)
                    af[r].x[t] = wmma::__float_to_tf32(af[r].x[t]);
            }
#pragma unroll
            for (int c = 0; c < 2; c++) {
                wmma::load_matrix_sync(bf[c],
                    &Bs[p][kk * BSTRIDE + wc * 32 + c * 16], BSTRIDE);
#pragma unroll
                for (int t = 0; t < bf[c].num_elements; t++)
                    bf[c].x[t] = wmma::__float_to_tf32(bf[c].x[t]);
            }
#pragma unroll
            for (int r = 0; r < 4; r++)
#pragma unroll
                for (int c = 0; c < 2; c++)
                    wmma::mma_sync(cf[r][c], af[r], bf[c], cf[r][c]);
        }
        p ^= 1;
    }
    __syncthreads();

    float* Cs = sm;                      // [128][CSTRIDE]
#pragma unroll
    for (int r = 0; r < 4; r++)
#pragma unroll
        for (int c = 0; c < 2; c++)
            wmma::store_matrix_sync(
                &Cs[(wr * 64 + r * 16) * CSTRIDE + wc * 32 + c * 16],
                cf[r][c], CSTRIDE, wmma::mem_row_major);
    __syncthreads();

    const int tx = tid & 15, ty = tid >> 4;
    float bi[8];
    *(float4*)&bi[0] = *(const float4*)(B + tx * 8);
    *(float4*)&bi[4] = *(const float4*)(B + tx * 8 + 4);
#pragma unroll
    for (int i = 0; i < 8; i++) {
        int rl = ty * 8 + i;
        int row = blockRow + rl;
        if (row >= NN) continue;
        float ov[8];
        *(float4*)&ov[0] = *(float4*)&Cs[rl * CSTRIDE + tx * 8];
        *(float4*)&ov[4] = *(float4*)&Cs[rl * CSTRIDE + tx * 8 + 4];
#pragma unroll
        for (int j = 0; j < 8; j++) ov[j] += bi[j];
        uint4 hv = pack_half8(ov);
        *(uint4*)(d_h16  + (size_t)row * HID + tx * 8) = hv;
        *(uint4*)(d_h016 + (size_t)row * HID + tx * 8) = hv;
    }
}

// ---------------- aggregation: s = 0.9*(norm-adj @ h) + 0.1*h0 ----------------
// TWO nodes per warp: lanes 0-15 -> node 2w, lanes 16-31 -> node 2w+1.
// Each lane owns a 16B chunk (8 halfs) of its node's row. 4-way edge unroll.
__global__ __launch_bounds__(256) void k_agg() {
    const int warpId = blockIdx.x * 8 + (threadIdx.x >> 5);
    const int lane = threadIdx.x & 31;
    const int sub = lane & 15;                // chunk id within row
    const int i = warpId * 2 + (lane >> 4);   // node (grid sized exactly)
    const uint4* h16 = (const uint4*)d_h16;   // 16 x 16B chunks per row

    float di = d_dinv[i];
    float wself = di * di;
    float a0[8], a1[8];
    {
        float sv[8];
        unpack_half8(__ldg(&h16[(size_t)i * 16 + sub]), sv);
#pragma unroll
        for (int j = 0; j < 8; j++) { a0[j] = wself * sv[j]; a1[j] = 0.f; }
    }

    const int beg = d_rowptr[i];
    const int end = d_rowptr[i + 1];
    int e = beg;
    while (__any_sync(0xffffffffu, e < end)) {
        int2 pp[4];
        float ww[4];
        uint4 vv[4];
#pragma unroll
        for (int k = 0; k < 4; k++) {
            int idx = e + k;
            bool valid = idx < end;
            idx = valid ? idx : 0;
            int2 p = __ldg(&d_epack[idx]);
            pp[k] = p;
            ww[k] = valid ? __int_as_float(p.y) : 0.f;
        }
#pragma unroll
        for (int k = 0; k < 4; k++)
            vv[k] = __ldg(&h16[(size_t)pp[k].x * 16 + sub]);
#pragma unroll
        for (int k = 0; k < 4; k++) {
            float v[8];
            unpack_half8(vv[k], v);
            float* acc = (k & 1) ? a1 : a0;
#pragma unroll
            for (int j = 0; j < 8; j++) acc[j] += ww[k] * v[j];
        }
        e += 4;
    }

    float h0v[8];
    unpack_half8(__ldg((const uint4*)d_h016 + (size_t)i * 16 + sub), h0v);
    float o[8];
#pragma unroll
    for (int j = 0; j < 8; j++)
        o[j] = 0.9f * (a0[j] + a1[j]) + 0.1f * h0v[j];
    ((uint4*)d_s16)[(size_t)i * 16 + sub] = pack_half8(o);
}

// ---------------- layer GEMM (fp16 HMMA) + identity-map mix + ELU ----------
// h = elu((1-beta)*s + beta*(s @ W)); s,W fp16; fp32 accumulate; one sync loop
__global__ __launch_bounds__(256, 2) void k_gemm_layer(int layer, float beta) {
    extern __shared__ float sm[];
    __half* Ah = (__half*)sm;                 // [128][AH_STRIDE]
    __half* Bh = Ah + 128 * AH_STRIDE;        // [128][AH_STRIDE]
    const int tid = threadIdx.x;
    const int blockRow = blockIdx.x * 128;
    const int warp = tid >> 5;
    const int wr = warp >> 2;
    const int wc = warp & 3;
    const __half* Wl = d_w16 + (size_t)layer * HID * HID;

    // load full A (s16) and B (w16) tiles: 2048 uint4 chunks each, 8/thread
#pragma unroll
    for (int j = 0; j < 8; j++) {
        int idx = tid + j * 256;
        int r = idx >> 4, c8 = idx & 15;
        int grow = blockRow + r;
        uint4 raw = make_uint4(0, 0, 0, 0);
        if (grow < NN)
            raw = *(const uint4*)(d_s16 + (size_t)grow * HID + c8 * 8);
        *(uint4*)&Ah[r * AH_STRIDE + c8 * 8] = raw;
    }
#pragma unroll
    for (int j = 0; j < 8; j++) {
        int idx = tid + j * 256;
        int r = idx >> 4, c8 = idx & 15;
        *(uint4*)&Bh[r * AH_STRIDE + c8 * 8] =
            *(const uint4*)(Wl + (size_t)r * HID + c8 * 8);
    }
    __syncthreads();

    wmma::fragment<wmma::accumulator, 16, 16, 16, float> cf[4][2];
#pragma unroll
    for (int r = 0; r < 4; r++)
#pragma unroll
        for (int c = 0; c < 2; c++)
            wmma::fill_fragment(cf[r][c], 0.f);

#pragma unroll
    for (int kk = 0; kk < 8; kk++) {
        wmma::fragment<wmma::matrix_a, 16, 16, 16, __half, wmma::row_major> af[4];
        wmma::fragment<wmma::matrix_b, 16, 16, 16, __half, wmma::row_major> bf[2];
#pragma unroll
        for (int r = 0; r < 4; r++)
            wmma::load_matrix_sync(af[r],
                &Ah[(wr * 64 + r * 16) * AH_STRIDE + kk * 16], AH_STRIDE);
#pragma unroll
        for (int c = 0; c < 2; c++)
            wmma::load_matrix_sync(bf[c],
                &Bh[(kk * 16) * AH_STRIDE + wc * 32 + c * 16], AH_STRIDE);
#pragma unroll
        for (int r = 0; r < 4; r++)
#pragma unroll
            for (int c = 0; c < 2; c++)
                wmma::mma_sync(cf[r][c], af[r], bf[c], cf[r][c]);
    }
    __syncthreads();   // all fragment reads done before C overlays Ah/Bh

    float* Cs = sm;                      // [128][CSTRIDE] fp32 overlay
#pragma unroll
    for (int r = 0; r < 4; r++)
#pragma unroll
        for (int c = 0; c < 2; c++)
            wmma::store_matrix_sync(
                &Cs[(wr * 64 + r * 16) * CSTRIDE + wc * 32 + c * 16],
                cf[r][c], CSTRIDE, wmma::mem_row_major);
    __syncthreads();

    const int tx = tid & 15, ty = tid >> 4;
    const float omb = 1.f - beta;
#pragma unroll
    for (int i = 0; i < 8; i++) {
        int rl = ty * 8 + i;
        int row = blockRow + rl;
        if (row >= NN) continue;
        float sv[8];
        uint4 sraw = *(const uint4*)(d_s16 + (size_t)row * HID + tx * 8);
        unpack_half8(sraw, sv);
        float av[8];
        *(float4*)&av[0] = *(float4*)&Cs[rl * CSTRIDE + tx * 8];
        *(float4*)&av[4] = *(float4*)&Cs[rl * CSTRIDE + tx * 8 + 4];
        float ov[8];
#pragma unroll
        for (int j = 0; j < 8; j++) {
            float v = omb * sv[j] + beta * av[j];
            ov[j] = (v > 0.f) ? v : expm1f(v);
        }
        *(uint4*)(d_h16 + (size_t)row * HID + tx * 8) = pack_half8(ov);
    }
}

// ---------------- output GEMM + log_softmax (+ counter re-zero) -------------
__global__ __launch_bounds__(256) void k_out(const float* __restrict__ Wo,
                                             const float* __restrict__ Bo,
                                             float* __restrict__ out) {
    int gid = blockIdx.x * blockDim.x + threadIdx.x;
    if (gid < NN) { d_cnt[gid] = 0; d_fill[gid] = 0; }

    __shared__ float ws[128][64];   // 32 KB
    __shared__ float hs[32][128];   // 16 KB
    const int tid = threadIdx.x;
    const int base = blockIdx.x * 32;
#pragma unroll
    for (int j = 0; j < 8; j++) {
        int idx = tid + j * 256;
        int r = idx >> 4, c4 = idx & 15;
        *(float4*)&ws[r][c4 * 4] = *(const float4*)(Wo + (size_t)r * NC + c4 * 4);
    }
#pragma unroll
    for (int j = 0; j < 2; j++) {
        int idx = tid + j * 256;
        int r = idx >> 4, c8 = idx & 15;
        uint4 raw = *(const uint4*)(d_h16 + (size_t)(base + r) * HID + c8 * 8);
        float v[8];
        unpack_half8(raw, v);
        *(float4*)&hs[r][c8 * 8]     = *(float4*)&v[0];
        *(float4*)&hs[r][c8 * 8 + 4] = *(float4*)&v[4];
    }
    __syncthreads();
    const int w = tid >> 5, lane = tid & 31;
    float b0 = Bo[lane], b1 = Bo[lane + 32];
    float acc[4][2];
#pragma unroll
    for (int r = 0; r < 4; r++) { acc[r][0] = 0.f; acc[r][1] = 0.f; }
    for (int k = 0; k < HID; k++) {
        float wv0 = ws[k][lane];
        float wv1 = ws[k][lane + 32];
#pragma unroll
        for (int r = 0; r < 4; r++) {
            float hv = hs[w * 4 + r][k];
            acc[r][0] += hv * wv0;
            acc[r][1] += hv * wv1;
        }
    }
#pragma unroll
    for (int r = 0; r < 4; r++) {
        int row = base + w * 4 + r;
        float v0 = acc[r][0] + b0;
        float v1 = acc[r][1] + b1;
        float m = fmaxf(v0, v1);
#pragma unroll
        for (int off = 16; off; off >>= 1)
            m = fmaxf(m, __shfl_xor_sync(0xffffffff, m, off));
        float ssum = expf(v0 - m) + expf(v1 - m);
#pragma unroll
        for (int off = 16; off; off >>= 1)
            ssum += __shfl_xor_sync(0xffffffff, ssum, off);
        float lse = m + logf(ssum);
        out[(size_t)row * NC + lane]      = v0 - lse;
        out[(size_t)row * NC + lane + 32] = v1 - lse;
    }
}

// ---------------- launch ----------------
extern "C" void kernel_launch(void* const* d_in, const int* in_sizes, int n_in,
                              void* d_out, int out_size) {
    const float* x      = (const float*)d_in[0];
    const void*  ei     = d_in[1];
    const float* w_in   = (const float*)d_in[2];
    const float* b_in   = (const float*)d_in[3];
    const float* conv_w = (const float*)d_in[4];
    const float* w_out  = (const float*)d_in[5];
    const float* b_out  = (const float*)d_in[6];
    float*       out    = (float*)d_out;

    cudaFuncSetAttribute(k_gemm_in_scatter,
                         cudaFuncAttributeMaxDynamicSharedMemorySize, INGEMM_SMEM);
    cudaFuncSetAttribute(k_gemm_layer,
                         cudaFuncAttributeMaxDynamicSharedMemorySize, LGEMM_SMEM);

    k_prep_edges<<<SC_BLOCKS, 256>>>(ei);                               // 0
    k_scan_dinv<<<1, 1024>>>();                                         // 1
    k_gemm_in_scatter<<<GEMM_BLOCKS + SC_BLOCKS, 256, INGEMM_SMEM>>>(
        x, w_in, b_in);                                                 // 2

    for (int l = 0; l < NL; l++) {                                      // 3..
        float beta = (float)log(0.5 / (double)(l + 1) + 1.0);
        k_agg<<<NN / 16, 256>>>();                // slot 3 (l=0) = profiled
        if (l == 0)
            k_wconv<<<(NL * HID * HID / 4 + 255) / 256, 256>>>(conv_w);
        k_gemm_layer<<<GEMM_BLOCKS, 256, LGEMM_SMEM>>>(l, beta);
    }

    k_out<<<NN / 32, 256>>>(w_out, b_out, out);
}